// round 10
// baseline (speedup 1.0000x reference)
#include <cuda_runtime.h>
#include <cuda_fp16.h>
#include <cstdint>

// ---------------- problem constants ----------------
#define NROWS 50000
#define MROWS 20000
#define NNZ_HHT 1600000
#define NNZ_H   1000000
#define NNZ_HT  1000000
#define NNZ_HTH 640000
#define NNZ_TOT (NNZ_HHT + NNZ_H + NNZ_HT + NNZ_HTH)
#define NEG_SLOPE 0.2f

// ---------------- half scratch (element counts) ----------------
#define H_XW0   0L
#define H_YW0   (H_XW0  + 12800000L)
#define H_X1    (H_YW0  + 5120000L)
#define H_Y1    (H_X1   + 12800000L)
#define H_X1W1  (H_Y1   + 5120000L)
#define H_Y1W1  (H_X1W1 + 3200000L)
#define HS_TOT  (H_Y1W1 + 1280000L)

// ---------------- int scratch ----------------
#define I_CUR   0L
#define I_RP    (I_CUR + 2L*NROWS + 2L*MROWS)
#define IS_TOT  (I_RP  + 2L*(NROWS+1) + 2L*(MROWS+1))

#define CUR_HHT 0L
#define CUR_H   ((long)NROWS)
#define CUR_HT  (2L*NROWS)
#define CUR_HTH (2L*NROWS + MROWS)
#define RP_HHT  0L
#define RP_H    ((long)NROWS + 1)
#define RP_HT   (2L*(NROWS + 1))
#define RP_HTH  (2L*(NROWS + 1) + MROWS + 1)
#define CS_HHT  0L
#define CS_H    ((long)NNZ_HHT)
#define CS_HT   ((long)NNZ_HHT + NNZ_H)
#define CS_HTH  ((long)NNZ_HHT + NNZ_H + NNZ_HT)

__device__ __align__(16) __half g_hs[HS_TOT];
__device__ __align__(16) int    g_is[IS_TOT];
__device__ __align__(16) int2   g_pack[NNZ_TOT];

__device__ __forceinline__ float leaky(float v) {
    return v >= 0.f ? v : NEG_SLOPE * v;
}

// ---------------- zero ints ----------------
__global__ void zero_i(int* __restrict__ p, int n) {
    int i = blockIdx.x * blockDim.x + threadIdx.x;
    if (i < n) p[i] = 0;
}

// ---------------- CSR build: count ----------------
__global__ void count_all_k(const int* __restrict__ r0, const int* __restrict__ r1,
                            const int* __restrict__ r2, const int* __restrict__ r3,
                            int* __restrict__ cur) {
    long i = (long)blockIdx.x * blockDim.x + threadIdx.x;
    if (i >= NNZ_TOT) return;
    if (i < NNZ_HHT) {
        atomicAdd(&cur[CUR_HHT + r0[i]], 1);
    } else if (i < NNZ_HHT + NNZ_H) {
        atomicAdd(&cur[CUR_H + r1[i - NNZ_HHT]], 1);
    } else if (i < NNZ_HHT + NNZ_H + NNZ_HT) {
        atomicAdd(&cur[CUR_HT + r2[i - NNZ_HHT - NNZ_H]], 1);
    } else {
        atomicAdd(&cur[CUR_HTH + r3[i - NNZ_HHT - NNZ_H - NNZ_HT]], 1);
    }
}

// ---------------- CSR build: fast single-pass scan (4 blocks) ----------------
__global__ void scan_all_k(int* __restrict__ cur, int* __restrict__ rp) {
    __shared__ int wsum[32];
    int b = blockIdx.x;
    int n; int* cnt; int* rowp;
    if (b == 0)      { n = NROWS; cnt = cur + CUR_HHT; rowp = rp + RP_HHT; }
    else if (b == 1) { n = NROWS; cnt = cur + CUR_H;   rowp = rp + RP_H;   }
    else if (b == 2) { n = MROWS; cnt = cur + CUR_HT;  rowp = rp + RP_HT;  }
    else             { n = MROWS; cnt = cur + CUR_HTH; rowp = rp + RP_HTH; }

    int t = threadIdx.x;            // 1024 threads
    int lane = t & 31, wid = t >> 5;
    int CH = (n + 1023) >> 10;
    int s0 = t * CH; if (s0 > n) s0 = n;
    int s1 = s0 + CH; if (s1 > n) s1 = n;

    int sum = 0;
    for (int i = s0; i < s1; i++) sum += cnt[i];

    int v = sum;
    #pragma unroll
    for (int o = 1; o < 32; o <<= 1) {
        int u = __shfl_up_sync(0xffffffffu, v, o);
        if (lane >= o) v += u;
    }
    if (lane == 31) wsum[wid] = v;
    __syncthreads();
    if (wid == 0) {
        int w = wsum[lane];
        #pragma unroll
        for (int o = 1; o < 32; o <<= 1) {
            int u = __shfl_up_sync(0xffffffffu, w, o);
            if (lane >= o) w += u;
        }
        wsum[lane] = w;
    }
    __syncthreads();
    int excl = v - sum + (wid ? wsum[wid - 1] : 0);

    int run = excl;
    for (int i = s0; i < s1; i++) {
        int c = cnt[i];
        rowp[i] = run;
        cnt[i] = run;
        run += c;
    }
    if (t == 1023) rowp[n] = run;
}

// ---------------- CSR build: permute, packed, 4 nnz per thread ----------------
struct Ent { int r, c; float v; long cs; int* cu; };

__device__ __forceinline__ Ent load_ent(long i,
    const int* r0, const int* c0, const float* v0,
    const int* r1, const int* c1, const float* v1,
    const int* r2, const int* c2, const float* v2,
    const int* r3, const int* c3, const float* v3, int* cur) {
    Ent e;
    if (i < NNZ_HHT) {
        e.r = r0[i]; e.c = c0[i]; e.v = v0[i]; e.cs = CS_HHT; e.cu = cur + CUR_HHT;
    } else if (i < NNZ_HHT + NNZ_H) {
        long j = i - NNZ_HHT;
        e.r = r1[j]; e.c = c1[j]; e.v = v1[j]; e.cs = CS_H; e.cu = cur + CUR_H;
    } else if (i < NNZ_HHT + NNZ_H + NNZ_HT) {
        long j = i - NNZ_HHT - NNZ_H;
        e.r = r2[j]; e.c = c2[j]; e.v = v2[j]; e.cs = CS_HT; e.cu = cur + CUR_HT;
    } else {
        long j = i - NNZ_HHT - NNZ_H - NNZ_HT;
        e.r = r3[j]; e.c = c3[j]; e.v = v3[j]; e.cs = CS_HTH; e.cu = cur + CUR_HTH;
    }
    return e;
}

__global__ void permute_all_k(const int* __restrict__ r0, const int* __restrict__ c0, const float* __restrict__ v0,
                              const int* __restrict__ r1, const int* __restrict__ c1, const float* __restrict__ v1,
                              const int* __restrict__ r2, const int* __restrict__ c2, const float* __restrict__ v2,
                              const int* __restrict__ r3, const int* __restrict__ c3, const float* __restrict__ v3,
                              int* __restrict__ cur, int2* __restrict__ pack) {
    long base = ((long)blockIdx.x * blockDim.x + threadIdx.x) * 4;
    if (base >= NNZ_TOT) return;
    Ent e[4];
    int cnt = 0;
    #pragma unroll
    for (int q = 0; q < 4; q++) {
        if (base + q < NNZ_TOT) {
            e[q] = load_ent(base + q, r0,c0,v0, r1,c1,v1, r2,c2,v2, r3,c3,v3, cur);
            cnt = q + 1;
        }
    }
    int slot[4];
    #pragma unroll
    for (int q = 0; q < 4; q++)
        if (q < cnt) slot[q] = atomicAdd(&e[q].cu[e[q].r], 1);
    #pragma unroll
    for (int q = 0; q < 4; q++)
        if (q < cnt) pack[e[q].cs + slot[q]] = make_int2(e[q].c, __float_as_int(e[q].v));
}

// ---------------- tensor-core GEMM: C[Rows,Ncols] = A @ W,  K=256 ----------------
__device__ __forceinline__ void mma16816(float* c, const unsigned* a, const unsigned* b) {
    asm volatile("mma.sync.aligned.m16n8k16.row.col.f32.f16.f16.f32 "
                 "{%0,%1,%2,%3}, {%4,%5,%6,%7}, {%8,%9}, {%0,%1,%2,%3};"
                 : "+f"(c[0]), "+f"(c[1]), "+f"(c[2]), "+f"(c[3])
                 : "r"(a[0]), "r"(a[1]), "r"(a[2]), "r"(a[3]),
                   "r"(b[0]), "r"(b[1]));
}

template<int AHALF>
__global__ void gemm2_mma(const void* __restrict__ A1v, int Rows1,
                          const void* __restrict__ A2v, int Rows2,
                          const float* __restrict__ W,
                          __half* __restrict__ C1, __half* __restrict__ C2,
                          int Ncols, int nb1) {
    const int BK = 32;
    __shared__ __align__(16) __half As[64][40];
    __shared__ __align__(16) __half Bs[64][40];

    const void* Av;
    __half* C;
    int Rows, m0;
    if ((int)blockIdx.y < nb1) { Av = A1v; C = C1; Rows = Rows1; m0 = blockIdx.y * 64; }
    else                        { Av = A2v; C = C2; Rows = Rows2; m0 = (blockIdx.y - nb1) * 64; }

    int tid = threadIdx.x;
    int lane = tid & 31, warp = tid >> 5;
    int wm = warp >> 2;
    int wn = warp & 3;
    int n0 = blockIdx.x * 64;

    float c[2][2][4] = {};

    for (int k0 = 0; k0 < 256; k0 += BK) {
        {
            int m  = tid >> 2;
            int kc = (tid & 3) * 8;
            int gm = m0 + m;
            __half h[8];
            if (gm < Rows) {
                if (AHALF) {
                    const __half* A = (const __half*)Av;
                    *(uint4*)h = *(const uint4*)(A + (long)gm * 256 + k0 + kc);
                } else {
                    const float* A = (const float*)Av;
                    float4 f0 = *(const float4*)(A + (long)gm * 256 + k0 + kc);
                    float4 f1 = *(const float4*)(A + (long)gm * 256 + k0 + kc + 4);
                    h[0] = __float2half(f0.x); h[1] = __float2half(f0.y);
                    h[2] = __float2half(f0.z); h[3] = __float2half(f0.w);
                    h[4] = __float2half(f1.x); h[5] = __float2half(f1.y);
                    h[6] = __float2half(f1.z); h[7] = __float2half(f1.w);
                }
            } else {
                #pragma unroll
                for (int q = 0; q < 8; q++) h[q] = __float2half(0.f);
            }
            *(uint4*)&As[m][kc] = *(uint4*)h;
        }
        {
            int n  = tid & 63;
            int k8 = (tid >> 6) * 8;
            #pragma unroll
            for (int q = 0; q < 8; q++) {
                float w = W[(long)(k0 + k8 + q) * Ncols + n0 + n];
                Bs[n][k8 + q] = __float2half(w);
            }
        }
        __syncthreads();

        #pragma unroll
        for (int ks = 0; ks < 2; ks++) {
            int kk = ks * 16;
            int gr = lane >> 2;
            int gk = (lane & 3) * 2;
            unsigned bf[2][2];
            #pragma unroll
            for (int j = 0; j < 2; j++) {
                int nn = wn * 16 + j * 8 + gr;
                bf[j][0] = *(const unsigned*)&Bs[nn][kk + gk];
                bf[j][1] = *(const unsigned*)&Bs[nn][kk + gk + 8];
            }
            #pragma unroll
            for (int i = 0; i < 2; i++) {
                int r = wm * 32 + i * 16 + gr;
                unsigned a[4];
                a[0] = *(const unsigned*)&As[r][kk + gk];
                a[1] = *(const unsigned*)&As[r + 8][kk + gk];
                a[2] = *(const unsigned*)&As[r][kk + gk + 8];
                a[3] = *(const unsigned*)&As[r + 8][kk + gk + 8];
                mma16816(c[i][0], a, bf[0]);
                mma16816(c[i][1], a, bf[1]);
            }
        }
        __syncthreads();
    }

    int gr = lane >> 2;
    int gc = (lane & 3) * 2;
    #pragma unroll
    for (int i = 0; i < 2; i++) {
        #pragma unroll
        for (int j = 0; j < 2; j++) {
            int rg = m0 + wm * 32 + i * 16 + gr;
            int cg = n0 + wn * 16 + j * 8 + gc;
            if (rg < Rows) {
                __half2 h = __floats2half2_rn(c[i][j][0], c[i][j][1]);
                *(__half2*)(C + (long)rg * Ncols + cg) = h;
            }
            if (rg + 8 < Rows) {
                __half2 h = __floats2half2_rn(c[i][j][2], c[i][j][3]);
                *(__half2*)(C + (long)(rg + 8) * Ncols + cg) = h;
            }
        }
    }
}

// ---------------- F=256 gather accumulate, MLP=8, packed index stream ----------------
__device__ __forceinline__ void macc8(float* acc, float4 raw, float v) {
    const __half2* h = (const __half2*)&raw;
    #pragma unroll
    for (int q = 0; q < 4; q++) {
        float2 f = __half22float2(h[q]);
        acc[q * 2 + 0] += v * f.x;
        acc[q * 2 + 1] += v * f.y;
    }
}

__device__ __forceinline__ void accum256(const int2* __restrict__ pack,
                                         int s, int e, const __half* __restrict__ dense,
                                         int lane, float* acc) {
    int j = s;
    if (j + 8 <= e) {
        int2 p[8];
        #pragma unroll
        for (int q = 0; q < 8; q++) p[q] = __ldg(pack + j + q);
        while (j + 8 <= e) {
            float4 r[8];
            #pragma unroll
            for (int q = 0; q < 8; q++)
                r[q] = ((const float4*)(dense + (long)p[q].x * 256))[lane];
            float w[8];
            #pragma unroll
            for (int q = 0; q < 8; q++) w[q] = __int_as_float(p[q].y);
            j += 8;
            if (j + 8 <= e) {
                #pragma unroll
                for (int q = 0; q < 8; q++) p[q] = __ldg(pack + j + q);
            }
            #pragma unroll
            for (int q = 0; q < 8; q++) macc8(acc, r[q], w[q]);
        }
    }
    for (; j < e; j++) {
        int2 p = __ldg(pack + j);
        float4 r = ((const float4*)(dense + (long)p.x * 256))[lane];
        macc8(acc, r, __int_as_float(p.y));
    }
}

// ---------------- combined F=256 dual SpMM + leaky -> fp16 output ----------------
__global__ void spmm256_all(const int* __restrict__ rp, const int2* __restrict__ pack,
                            const __half* __restrict__ dX, const __half* __restrict__ dY,
                            __half* __restrict__ x1h, __half* __restrict__ y1h) {
    int w = (blockIdx.x * blockDim.x + threadIdx.x) >> 5;
    if (w >= NROWS + MROWS) return;
    int lane = threadIdx.x & 31;

    const int* rpA; const int* rpB; long csA, csB; __half* outp; int r;
    if (w < NROWS) {
        r = w;
        rpA = rp + RP_HHT; csA = CS_HHT;
        rpB = rp + RP_H;   csB = CS_H;
        outp = x1h;
    } else {
        r = w - NROWS;
        rpA = rp + RP_HT;  csA = CS_HT;
        rpB = rp + RP_HTH; csB = CS_HTH;
        outp = y1h;
    }

    float a[8] = {}, b[8] = {};
    accum256(pack + csA, rpA[r], rpA[r + 1], dX, lane, a);
    accum256(pack + csB, rpB[r], rpB[r + 1], dY, lane, b);

    __half2 h[4];
    #pragma unroll
    for (int q = 0; q < 4; q++)
        h[q] = __floats2half2_rn(leaky(a[q * 2]) + leaky(b[q * 2]),
                                 leaky(a[q * 2 + 1]) + leaky(b[q * 2 + 1]));
    uint4 u;
    u.x = *(unsigned*)&h[0]; u.y = *(unsigned*)&h[1];
    u.z = *(unsigned*)&h[2]; u.w = *(unsigned*)&h[3];
    *((uint4*)(outp + (long)r * 256) + lane) = u;
}

// ---------------- F=64 gather accumulate, MLP=8, packed ----------------
__device__ __forceinline__ void accum64(const int2* __restrict__ pack,
                                        int s, int e, const __half* __restrict__ dense,
                                        int lane, float2& acc) {
    int j = s;
    if (j + 8 <= e) {
        int2 p[8];
        #pragma unroll
        for (int q = 0; q < 8; q++) p[q] = __ldg(pack + j + q);
        while (j + 8 <= e) {
            __half2 h[8];
            #pragma unroll
            for (int q = 0; q < 8; q++)
                h[q] = ((const __half2*)(dense + (long)p[q].x * 64))[lane];
            float w[8];
            #pragma unroll
            for (int q = 0; q < 8; q++) w[q] = __int_as_float(p[q].y);
            j += 8;
            if (j + 8 <= e) {
                #pragma unroll
                for (int q = 0; q < 8; q++) p[q] = __ldg(pack + j + q);
            }
            #pragma unroll
            for (int q = 0; q < 8; q++) {
                float2 f = __half22float2(h[q]);
                acc.x += w[q] * f.x;
                acc.y += w[q] * f.y;
            }
        }
    }
    for (; j < e; j++) {
        int2 p = __ldg(pack + j);
        float2 f = __half22float2(((const __half2*)(dense + (long)p.x * 64))[lane]);
        float v = __int_as_float(p.y);
        acc.x += v * f.x; acc.y += v * f.y;
    }
}

// ---------------- combined F=64 dual SpMM + leaky straight into d_out ----------------
__global__ void spmm64_all(const int* __restrict__ rp, const int2* __restrict__ pack,
                           const __half* __restrict__ dX, const __half* __restrict__ dY,
                           float* __restrict__ outbase) {
    int w = (blockIdx.x * blockDim.x + threadIdx.x) >> 5;
    if (w >= NROWS + MROWS) return;
    int lane = threadIdx.x & 31;

    const int* rpA; const int* rpB; long csA, csB; int r;
    if (w < NROWS) {
        r = w;
        rpA = rp + RP_HHT; csA = CS_HHT;
        rpB = rp + RP_H;   csB = CS_H;
    } else {
        r = w - NROWS;
        rpA = rp + RP_HT;  csA = CS_HT;
        rpB = rp + RP_HTH; csB = CS_HTH;
    }

    float2 a = make_float2(0, 0), b = a;
    accum64(pack + csA, rpA[r], rpA[r + 1], dX, lane, a);
    accum64(pack + csB, rpB[r], rpB[r + 1], dY, lane, b);

    float2 res;
    res.x = leaky(a.x) + leaky(b.x);
    res.y = leaky(a.y) + leaky(b.y);
    ((float2*)(outbase + (long)w * 64))[lane] = res;
}

// ---------------- side-stream handles ----------------
static cudaStream_t g_side = nullptr;
static cudaEvent_t  g_fork = nullptr;
static cudaEvent_t  g_join = nullptr;

extern "C" void kernel_launch(void* const* d_in, const int* in_sizes, int n_in,
                              void* d_out, int out_size) {
    const float* x  = (const float*)d_in[0];
    const float* y  = (const float*)d_in[1];
    const float* W0 = (const float*)d_in[2];
    const float* W1 = (const float*)d_in[3];
    const int*   hht_r = (const int*)d_in[4];
    const int*   hht_c = (const int*)d_in[5];
    const float* hht_v = (const float*)d_in[6];
    const int*   h_r = (const int*)d_in[7];
    const int*   h_c = (const int*)d_in[8];
    const float* h_v = (const float*)d_in[9];
    const int*   ht_r = (const int*)d_in[10];
    const int*   ht_c = (const int*)d_in[11];
    const float* ht_v = (const float*)d_in[12];
    const int*   hth_r = (const int*)d_in[13];
    const int*   hth_c = (const int*)d_in[14];
    const float* hth_v = (const float*)d_in[15];
    float* out = (float*)d_out;

    if (!g_side) {
        cudaStreamCreateWithFlags(&g_side, cudaStreamNonBlocking);
        cudaEventCreateWithFlags(&g_fork, cudaEventDisableTiming);
        cudaEventCreateWithFlags(&g_join, cudaEventDisableTiming);
    }

    void* p = nullptr;
    cudaGetSymbolAddress(&p, g_hs);
    __half* H = (__half*)p;
    cudaGetSymbolAddress(&p, g_is);
    int* I = (int*)p;
    cudaGetSymbolAddress(&p, g_pack);
    int2* pack = (int2*)p;

    __half* xw0  = H + H_XW0;
    __half* yw0  = H + H_YW0;
    __half* x1h  = H + H_X1;
    __half* y1h  = H + H_Y1;
    __half* x1w1 = H + H_X1W1;
    __half* y1w1 = H + H_Y1W1;

    int* cur = I + I_CUR;
    int* rp  = I + I_RP;

    const int T = 256;

    // ---- fork: CSR build on side stream, layer-0 GEMM on main stream ----
    cudaEventRecord(g_fork, 0);
    cudaStreamWaitEvent(g_side, g_fork, 0);

    {   // side stream: CSR build
        int ncur = 2 * NROWS + 2 * MROWS;
        zero_i<<<(ncur + T - 1) / T, T, 0, g_side>>>(cur, ncur);
        count_all_k<<<(NNZ_TOT + T - 1) / T, T, 0, g_side>>>(hht_r, h_r, ht_r, hth_r, cur);
        scan_all_k<<<4, 1024, 0, g_side>>>(cur, rp);
        permute_all_k<<<(NNZ_TOT / 4 + T - 1) / T, T, 0, g_side>>>(hht_r, hht_c, hht_v,
                                                                   h_r, h_c, h_v,
                                                                   ht_r, ht_c, ht_v,
                                                                   hth_r, hth_c, hth_v,
                                                                   cur, pack);
        cudaEventRecord(g_join, g_side);
    }

    {   // main stream: layer-0 GEMMs (fp32 A -> fp16 mma)
        int nb1 = (NROWS + 63) / 64, nb2 = (MROWS + 63) / 64;
        dim3 g(256 / 64, nb1 + nb2);
        gemm2_mma<0><<<g, T>>>(x, NROWS, y, MROWS, W0, xw0, yw0, 256, nb1);
    }

    // ---- join ----
    cudaStreamWaitEvent(0, g_join, 0);

    // ---- layer-0 SpMM (combined) -> fp16 x1/y1 ----
    spmm256_all<<<(NROWS + MROWS + 7) / 8, T>>>(rp, pack, xw0, yw0, x1h, y1h);

    // ---- layer-1 GEMMs (fp16 A mma) ----
    {
        int nb1 = (NROWS + 63) / 64, nb2 = (MROWS + 63) / 64;
        dim3 g(64 / 64, nb1 + nb2);
        gemm2_mma<1><<<g, T>>>(x1h, NROWS, y1h, MROWS, W1, x1w1, y1w1, 64, nb1);
    }

    // ---- layer-1 SpMM (combined) straight into d_out ----
    spmm64_all<<<(NROWS + MROWS + 7) / 8, T>>>(rp, pack, x1w1, y1w1, out);
}

// round 12
// speedup vs baseline: 1.0431x; 1.0431x over previous
#include <cuda_runtime.h>
#include <cuda_fp16.h>
#include <cstdint>

// ---------------- problem constants ----------------
#define NROWS 50000
#define MROWS 20000
#define NNZ_HHT 1600000
#define NNZ_H   1000000
#define NNZ_HT  1000000
#define NNZ_HTH 640000
#define NNZ_TOT (NNZ_HHT + NNZ_H + NNZ_HT + NNZ_HTH)
#define NEG_SLOPE 0.2f

// ---------------- half scratch (element counts) ----------------
#define H_XW0   0L
#define H_YW0   (H_XW0  + 12800000L)
#define H_X1    (H_YW0  + 5120000L)
#define H_Y1    (H_X1   + 12800000L)
#define H_X1W1  (H_Y1   + 5120000L)
#define H_Y1W1  (H_X1W1 + 3200000L)
#define HS_TOT  (H_Y1W1 + 1280000L)

// ---------------- int scratch ----------------
#define I_CUR   0L
#define I_RP    (I_CUR + 2L*NROWS + 2L*MROWS)
#define IS_TOT  (I_RP  + 2L*(NROWS+1) + 2L*(MROWS+1))

#define CUR_HHT 0L
#define CUR_H   ((long)NROWS)
#define CUR_HT  (2L*NROWS)
#define CUR_HTH (2L*NROWS + MROWS)
#define RP_HHT  0L
#define RP_H    ((long)NROWS + 1)
#define RP_HT   (2L*(NROWS + 1))
#define RP_HTH  (2L*(NROWS + 1) + MROWS + 1)
#define CS_HHT  0L
#define CS_H    ((long)NNZ_HHT)
#define CS_HT   ((long)NNZ_HHT + NNZ_H)
#define CS_HTH  ((long)NNZ_HHT + NNZ_H + NNZ_HT)

__device__ __align__(16) __half g_hs[HS_TOT];
__device__ __align__(16) int    g_is[IS_TOT];
__device__ __align__(16) int2   g_pack[NNZ_TOT];

__device__ __forceinline__ float leaky(float v) {
    return v >= 0.f ? v : NEG_SLOPE * v;
}

// ---------------- CSR build: count ----------------
__global__ void count_all_k(const int* __restrict__ r0, const int* __restrict__ r1,
                            const int* __restrict__ r2, const int* __restrict__ r3,
                            int* __restrict__ cur) {
    long i = (long)blockIdx.x * blockDim.x + threadIdx.x;
    if (i >= NNZ_TOT) return;
    if (i < NNZ_HHT) {
        atomicAdd(&cur[CUR_HHT + r0[i]], 1);
    } else if (i < NNZ_HHT + NNZ_H) {
        atomicAdd(&cur[CUR_H + r1[i - NNZ_HHT]], 1);
    } else if (i < NNZ_HHT + NNZ_H + NNZ_HT) {
        atomicAdd(&cur[CUR_HT + r2[i - NNZ_HHT - NNZ_H]], 1);
    } else {
        atomicAdd(&cur[CUR_HTH + r3[i - NNZ_HHT - NNZ_H - NNZ_HT]], 1);
    }
}

// ---------------- CSR build: fast single-pass scan (4 blocks) ----------------
__global__ void scan_all_k(int* __restrict__ cur, int* __restrict__ rp) {
    __shared__ int wsum[32];
    int b = blockIdx.x;
    int n; int* cnt; int* rowp;
    if (b == 0)      { n = NROWS; cnt = cur + CUR_HHT; rowp = rp + RP_HHT; }
    else if (b == 1) { n = NROWS; cnt = cur + CUR_H;   rowp = rp + RP_H;   }
    else if (b == 2) { n = MROWS; cnt = cur + CUR_HT;  rowp = rp + RP_HT;  }
    else             { n = MROWS; cnt = cur + CUR_HTH; rowp = rp + RP_HTH; }

    int t = threadIdx.x;            // 1024 threads
    int lane = t & 31, wid = t >> 5;
    int CH = (n + 1023) >> 10;
    int s0 = t * CH; if (s0 > n) s0 = n;
    int s1 = s0 + CH; if (s1 > n) s1 = n;

    int sum = 0;
    for (int i = s0; i < s1; i++) sum += cnt[i];

    int v = sum;
    #pragma unroll
    for (int o = 1; o < 32; o <<= 1) {
        int u = __shfl_up_sync(0xffffffffu, v, o);
        if (lane >= o) v += u;
    }
    if (lane == 31) wsum[wid] = v;
    __syncthreads();
    if (wid == 0) {
        int w = wsum[lane];
        #pragma unroll
        for (int o = 1; o < 32; o <<= 1) {
            int u = __shfl_up_sync(0xffffffffu, w, o);
            if (lane >= o) w += u;
        }
        wsum[lane] = w;
    }
    __syncthreads();
    int excl = v - sum + (wid ? wsum[wid - 1] : 0);

    int run = excl;
    for (int i = s0; i < s1; i++) {
        int c = cnt[i];
        rowp[i] = run;
        cnt[i] = run;
        run += c;
    }
    if (t == 1023) rowp[n] = run;
}

// ---------------- CSR build: permute over a range, ILP=2 ----------------
struct Ent { int r, c; float v; long cs; int* cu; };

__device__ __forceinline__ Ent load_ent(long i,
    const int* r0, const int* c0, const float* v0,
    const int* r1, const int* c1, const float* v1,
    const int* r2, const int* c2, const float* v2,
    const int* r3, const int* c3, const float* v3, int* cur) {
    Ent e;
    if (i < NNZ_HHT) {
        e.r = r0[i]; e.c = c0[i]; e.v = v0[i]; e.cs = CS_HHT; e.cu = cur + CUR_HHT;
    } else if (i < NNZ_HHT + NNZ_H) {
        long j = i - NNZ_HHT;
        e.r = r1[j]; e.c = c1[j]; e.v = v1[j]; e.cs = CS_H; e.cu = cur + CUR_H;
    } else if (i < NNZ_HHT + NNZ_H + NNZ_HT) {
        long j = i - NNZ_HHT - NNZ_H;
        e.r = r2[j]; e.c = c2[j]; e.v = v2[j]; e.cs = CS_HT; e.cu = cur + CUR_HT;
    } else {
        long j = i - NNZ_HHT - NNZ_H - NNZ_HT;
        e.r = r3[j]; e.c = c3[j]; e.v = v3[j]; e.cs = CS_HTH; e.cu = cur + CUR_HTH;
    }
    return e;
}

__global__ void permute_range_k(const int* __restrict__ r0, const int* __restrict__ c0, const float* __restrict__ v0,
                                const int* __restrict__ r1, const int* __restrict__ c1, const float* __restrict__ v1,
                                const int* __restrict__ r2, const int* __restrict__ c2, const float* __restrict__ v2,
                                const int* __restrict__ r3, const int* __restrict__ c3, const float* __restrict__ v3,
                                int* __restrict__ cur, int2* __restrict__ pack,
                                long start, long end) {
    long i = start + ((long)blockIdx.x * blockDim.x + threadIdx.x) * 2;
    if (i >= end) return;
    Ent e0 = load_ent(i, r0,c0,v0, r1,c1,v1, r2,c2,v2, r3,c3,v3, cur);
    bool two = (i + 1 < end);
    Ent e1;
    if (two) e1 = load_ent(i + 1, r0,c0,v0, r1,c1,v1, r2,c2,v2, r3,c3,v3, cur);
    int s0 = atomicAdd(&e0.cu[e0.r], 1);
    pack[e0.cs + s0] = make_int2(e0.c, __float_as_int(e0.v));
    if (two) {
        int s1 = atomicAdd(&e1.cu[e1.r], 1);
        pack[e1.cs + s1] = make_int2(e1.c, __float_as_int(e1.v));
    }
}

// ---------------- tensor-core GEMM: C[Rows,Ncols] = A @ W,  K=256 ----------------
__device__ __forceinline__ void mma16816(float* c, const unsigned* a, const unsigned* b) {
    asm volatile("mma.sync.aligned.m16n8k16.row.col.f32.f16.f16.f32 "
                 "{%0,%1,%2,%3}, {%4,%5,%6,%7}, {%8,%9}, {%0,%1,%2,%3};"
                 : "+f"(c[0]), "+f"(c[1]), "+f"(c[2]), "+f"(c[3])
                 : "r"(a[0]), "r"(a[1]), "r"(a[2]), "r"(a[3]),
                   "r"(b[0]), "r"(b[1]));
}

template<int AHALF>
__global__ void gemm2_mma(const void* __restrict__ A1v, int Rows1,
                          const void* __restrict__ A2v, int Rows2,
                          const float* __restrict__ W,
                          __half* __restrict__ C1, __half* __restrict__ C2,
                          int Ncols, int nb1) {
    const int BK = 32;
    __shared__ __align__(16) __half As[64][40];
    __shared__ __align__(16) __half Bs[64][40];

    const void* Av;
    __half* C;
    int Rows, m0;
    if ((int)blockIdx.y < nb1) { Av = A1v; C = C1; Rows = Rows1; m0 = blockIdx.y * 64; }
    else                        { Av = A2v; C = C2; Rows = Rows2; m0 = (blockIdx.y - nb1) * 64; }

    int tid = threadIdx.x;
    int lane = tid & 31, warp = tid >> 5;
    int wm = warp >> 2;
    int wn = warp & 3;
    int n0 = blockIdx.x * 64;

    float c[2][2][4] = {};

    for (int k0 = 0; k0 < 256; k0 += BK) {
        {
            int m  = tid >> 2;
            int kc = (tid & 3) * 8;
            int gm = m0 + m;
            __half h[8];
            if (gm < Rows) {
                if (AHALF) {
                    const __half* A = (const __half*)Av;
                    *(uint4*)h = *(const uint4*)(A + (long)gm * 256 + k0 + kc);
                } else {
                    const float* A = (const float*)Av;
                    float4 f0 = *(const float4*)(A + (long)gm * 256 + k0 + kc);
                    float4 f1 = *(const float4*)(A + (long)gm * 256 + k0 + kc + 4);
                    h[0] = __float2half(f0.x); h[1] = __float2half(f0.y);
                    h[2] = __float2half(f0.z); h[3] = __float2half(f0.w);
                    h[4] = __float2half(f1.x); h[5] = __float2half(f1.y);
                    h[6] = __float2half(f1.z); h[7] = __float2half(f1.w);
                }
            } else {
                #pragma unroll
                for (int q = 0; q < 8; q++) h[q] = __float2half(0.f);
            }
            *(uint4*)&As[m][kc] = *(uint4*)h;
        }
        {
            int n  = tid & 63;
            int k8 = (tid >> 6) * 8;
            #pragma unroll
            for (int q = 0; q < 8; q++) {
                float w = W[(long)(k0 + k8 + q) * Ncols + n0 + n];
                Bs[n][k8 + q] = __float2half(w);
            }
        }
        __syncthreads();

        #pragma unroll
        for (int ks = 0; ks < 2; ks++) {
            int kk = ks * 16;
            int gr = lane >> 2;
            int gk = (lane & 3) * 2;
            unsigned bf[2][2];
            #pragma unroll
            for (int j = 0; j < 2; j++) {
                int nn = wn * 16 + j * 8 + gr;
                bf[j][0] = *(const unsigned*)&Bs[nn][kk + gk];
                bf[j][1] = *(const unsigned*)&Bs[nn][kk + gk + 8];
            }
            #pragma unroll
            for (int i = 0; i < 2; i++) {
                int r = wm * 32 + i * 16 + gr;
                unsigned a[4];
                a[0] = *(const unsigned*)&As[r][kk + gk];
                a[1] = *(const unsigned*)&As[r + 8][kk + gk];
                a[2] = *(const unsigned*)&As[r][kk + gk + 8];
                a[3] = *(const unsigned*)&As[r + 8][kk + gk + 8];
                mma16816(c[i][0], a, bf[0]);
                mma16816(c[i][1], a, bf[1]);
            }
        }
        __syncthreads();
    }

    int gr = lane >> 2;
    int gc = (lane & 3) * 2;
    #pragma unroll
    for (int i = 0; i < 2; i++) {
        #pragma unroll
        for (int j = 0; j < 2; j++) {
            int rg = m0 + wm * 32 + i * 16 + gr;
            int cg = n0 + wn * 16 + j * 8 + gc;
            if (rg < Rows) {
                __half2 h = __floats2half2_rn(c[i][j][0], c[i][j][1]);
                *(__half2*)(C + (long)rg * Ncols + cg) = h;
            }
            if (rg + 8 < Rows) {
                __half2 h = __floats2half2_rn(c[i][j][2], c[i][j][3]);
                *(__half2*)(C + (long)(rg + 8) * Ncols + cg) = h;
            }
        }
    }
}

// ---------------- F=256 gather accumulate, MLP=4 (R8-proven) ----------------
__device__ __forceinline__ void macc8(float* acc, float4 raw, float v) {
    const __half2* h = (const __half2*)&raw;
    #pragma unroll
    for (int q = 0; q < 4; q++) {
        float2 f = __half22float2(h[q]);
        acc[q * 2 + 0] += v * f.x;
        acc[q * 2 + 1] += v * f.y;
    }
}

__device__ __forceinline__ void accum256(const int2* __restrict__ pack,
                                         int s, int e, const __half* __restrict__ dense,
                                         int lane, float* acc) {
    int j = s;
    if (j + 4 <= e) {
        int2 p0 = __ldg(pack + j),     p1 = __ldg(pack + j + 1);
        int2 p2 = __ldg(pack + j + 2), p3 = __ldg(pack + j + 3);
        for (; j + 4 <= e; ) {
            float4 r0 = ((const float4*)(dense + (long)p0.x * 256))[lane];
            float4 r1 = ((const float4*)(dense + (long)p1.x * 256))[lane];
            float4 r2 = ((const float4*)(dense + (long)p2.x * 256))[lane];
            float4 r3 = ((const float4*)(dense + (long)p3.x * 256))[lane];
            float w0 = __int_as_float(p0.y), w1 = __int_as_float(p1.y);
            float w2 = __int_as_float(p2.y), w3 = __int_as_float(p3.y);
            j += 4;
            if (j + 4 <= e) {
                p0 = __ldg(pack + j);     p1 = __ldg(pack + j + 1);
                p2 = __ldg(pack + j + 2); p3 = __ldg(pack + j + 3);
            }
            macc8(acc, r0, w0);
            macc8(acc, r1, w1);
            macc8(acc, r2, w2);
            macc8(acc, r3, w3);
        }
    }
    for (; j < e; j++) {
        int2 p = __ldg(pack + j);
        float4 r = ((const float4*)(dense + (long)p.x * 256))[lane];
        macc8(acc, r, __int_as_float(p.y));
    }
}

// ---------------- F=256 dual SpMM + leaky over a row range -> fp16 ----------------
__global__ void spmm256_part(const int* __restrict__ rpA, const int2* __restrict__ packA,
                             const int* __restrict__ rpB, const int2* __restrict__ packB,
                             const __half* __restrict__ dA, const __half* __restrict__ dB,
                             __half* __restrict__ outp, int nrows) {
    int r = (blockIdx.x * blockDim.x + threadIdx.x) >> 5;
    if (r >= nrows) return;
    int lane = threadIdx.x & 31;

    float a[8] = {}, b[8] = {};
    accum256(packA, rpA[r], rpA[r + 1], dA, lane, a);
    accum256(packB, rpB[r], rpB[r + 1], dB, lane, b);

    __half2 h[4];
    #pragma unroll
    for (int q = 0; q < 4; q++)
        h[q] = __floats2half2_rn(leaky(a[q * 2]) + leaky(b[q * 2]),
                                 leaky(a[q * 2 + 1]) + leaky(b[q * 2 + 1]));
    uint4 u;
    u.x = *(unsigned*)&h[0]; u.y = *(unsigned*)&h[1];
    u.z = *(unsigned*)&h[2]; u.w = *(unsigned*)&h[3];
    *((uint4*)(outp + (long)r * 256) + lane) = u;
}

// ---------------- F=64 gather, 2 nnz per warp (half-warp per nnz) ----------------
__device__ __forceinline__ void vmacc4(float4& acc, uint2 d, float v) {
    float2 f0 = __half22float2(*(__half2*)&d.x);
    float2 f1 = __half22float2(*(__half2*)&d.y);
    acc.x += v * f0.x; acc.y += v * f0.y;
    acc.z += v * f1.x; acc.w += v * f1.y;
}

__device__ __forceinline__ void accum64v(const int2* __restrict__ pack,
                                         int s, int e, const __half* __restrict__ dense,
                                         int sub, int fl, float4& acc) {
    int j = s;
    for (; j + 4 <= e; j += 4) {
        int2 p0 = __ldg(pack + j + sub);
        int2 p1 = __ldg(pack + j + 2 + sub);
        uint2 d0 = *(const uint2*)(dense + (long)p0.x * 64 + fl * 4);
        uint2 d1 = *(const uint2*)(dense + (long)p1.x * 64 + fl * 4);
        vmacc4(acc, d0, __int_as_float(p0.y));
        vmacc4(acc, d1, __int_as_float(p1.y));
    }
    for (; j + 2 <= e; j += 2) {
        int2 p = __ldg(pack + j + sub);
        uint2 d = *(const uint2*)(dense + (long)p.x * 64 + fl * 4);
        vmacc4(acc, d, __int_as_float(p.y));
    }
    if (j < e) {
        int2 p = __ldg(pack + j);
        uint2 d = *(const uint2*)(dense + (long)p.x * 64 + fl * 4);
        float v = (sub == 0) ? __int_as_float(p.y) : 0.f;
        vmacc4(acc, d, v);
    }
}

__global__ void spmm64_all(const int* __restrict__ rp, const int2* __restrict__ pack,
                           const __half* __restrict__ dX, const __half* __restrict__ dY,
                           float* __restrict__ outbase) {
    int w = (blockIdx.x * blockDim.x + threadIdx.x) >> 5;
    if (w >= NROWS + MROWS) return;
    int lane = threadIdx.x & 31;
    int sub = lane >> 4;
    int fl  = lane & 15;

    const int* rpA; const int* rpB; long csA, csB; int r;
    if (w < NROWS) {
        r = w;
        rpA = rp + RP_HHT; csA = CS_HHT;
        rpB = rp + RP_H;   csB = CS_H;
    } else {
        r = w - NROWS;
        rpA = rp + RP_HT;  csA = CS_HT;
        rpB = rp + RP_HTH; csB = CS_HTH;
    }

    float4 a = make_float4(0, 0, 0, 0), b = a;
    accum64v(pack + csA, rpA[r], rpA[r + 1], dX, sub, fl, a);
    accum64v(pack + csB, rpB[r], rpB[r + 1], dY, sub, fl, b);

    a.x += __shfl_down_sync(0xffffffffu, a.x, 16);
    a.y += __shfl_down_sync(0xffffffffu, a.y, 16);
    a.z += __shfl_down_sync(0xffffffffu, a.z, 16);
    a.w += __shfl_down_sync(0xffffffffu, a.w, 16);
    b.x += __shfl_down_sync(0xffffffffu, b.x, 16);
    b.y += __shfl_down_sync(0xffffffffu, b.y, 16);
    b.z += __shfl_down_sync(0xffffffffu, b.z, 16);
    b.w += __shfl_down_sync(0xffffffffu, b.w, 16);

    if (sub == 0) {
        float4 res;
        res.x = leaky(a.x) + leaky(b.x);
        res.y = leaky(a.y) + leaky(b.y);
        res.z = leaky(a.z) + leaky(b.z);
        res.w = leaky(a.w) + leaky(b.w);
        ((float4*)(outbase + (long)w * 64))[fl] = res;
    }
}

// ---------------- side-stream handles ----------------
static cudaStream_t g_side = nullptr;
static cudaEvent_t  g_fork = nullptr;
static cudaEvent_t  g_evA = nullptr;
static cudaEvent_t  g_evB = nullptr;

extern "C" void kernel_launch(void* const* d_in, const int* in_sizes, int n_in,
                              void* d_out, int out_size) {
    const float* x  = (const float*)d_in[0];
    const float* y  = (const float*)d_in[1];
    const float* W0 = (const float*)d_in[2];
    const float* W1 = (const float*)d_in[3];
    const int*   hht_r = (const int*)d_in[4];
    const int*   hht_c = (const int*)d_in[5];
    const float* hht_v = (const float*)d_in[6];
    const int*   h_r = (const int*)d_in[7];
    const int*   h_c = (const int*)d_in[8];
    const float* h_v = (const float*)d_in[9];
    const int*   ht_r = (const int*)d_in[10];
    const int*   ht_c = (const int*)d_in[11];
    const float* ht_v = (const float*)d_in[12];
    const int*   hth_r = (const int*)d_in[13];
    const int*   hth_c = (const int*)d_in[14];
    const float* hth_v = (const float*)d_in[15];
    float* out = (float*)d_out;

    if (!g_side) {
        cudaStreamCreateWithFlags(&g_side, cudaStreamNonBlocking);
        cudaEventCreateWithFlags(&g_fork, cudaEventDisableTiming);
        cudaEventCreateWithFlags(&g_evA, cudaEventDisableTiming);
        cudaEventCreateWithFlags(&g_evB, cudaEventDisableTiming);
    }

    void* p = nullptr;
    cudaGetSymbolAddress(&p, g_hs);
    __half* H = (__half*)p;
    cudaGetSymbolAddress(&p, g_is);
    int* I = (int*)p;
    cudaGetSymbolAddress(&p, g_pack);
    int2* pack = (int2*)p;

    __half* xw0  = H + H_XW0;
    __half* yw0  = H + H_YW0;
    __half* x1h  = H + H_X1;
    __half* y1h  = H + H_Y1;
    __half* x1w1 = H + H_X1W1;
    __half* y1w1 = H + H_Y1W1;

    int* cur = I + I_CUR;
    int* rp  = I + I_RP;

    const int T = 256;
    const long SPLIT = (long)NNZ_HHT + NNZ_H;   // x-rows use HHT+H; y-rows use HT+HTH

    // ---- fork: CSR build on side stream, layer-0 GEMM on main stream ----
    cudaEventRecord(g_fork, 0);
    cudaStreamWaitEvent(g_side, g_fork, 0);

    {   // side stream: CSR build (zero as memset node, not a kernel)
        int ncur = 2 * NROWS + 2 * MROWS;
        cudaMemsetAsync(cur, 0, (size_t)ncur * sizeof(int), g_side);
        count_all_k<<<(NNZ_TOT + T - 1) / T, T, 0, g_side>>>(hht_r, h_r, ht_r, hth_r, cur);
        scan_all_k<<<4, 1024, 0, g_side>>>(cur, rp);
        // permute A: HHT + H entries (needed by spmm256 x-part)
        permute_range_k<<<(int)((SPLIT / 2 + T - 1) / T), T, 0, g_side>>>(
            hht_r, hht_c, hht_v, h_r, h_c, h_v, ht_r, ht_c, ht_v,
            hth_r, hth_c, hth_v, cur, pack, 0L, SPLIT);
        cudaEventRecord(g_evA, g_side);
        // permute B: HT + HTH entries (needed by spmm256 y-part / spmm64)
        permute_range_k<<<(int)(((NNZ_TOT - SPLIT) / 2 + T - 1) / T), T, 0, g_side>>>(
            hht_r, hht_c, hht_v, h_r, h_c, h_v, ht_r, ht_c, ht_v,
            hth_r, hth_c, hth_v, cur, pack, SPLIT, (long)NNZ_TOT);
        cudaEventRecord(g_evB, g_side);
    }

    {   // main stream: layer-0 GEMMs (fp32 A -> fp16 mma)
        int nb1 = (NROWS + 63) / 64, nb2 = (MROWS + 63) / 64;
        dim3 g(256 / 64, nb1 + nb2);
        gemm2_mma<0><<<g, T>>>(x, NROWS, y, MROWS, W0, xw0, yw0, 256, nb1);
    }

    // ---- layer-0 SpMM x-part (needs permute A only) — overlaps permute B ----
    cudaStreamWaitEvent(0, g_evA, 0);
    spmm256_part<<<(NROWS + 7) / 8, T>>>(rp + RP_HHT, pack + CS_HHT,
                                         rp + RP_H,   pack + CS_H,
                                         xw0, yw0, x1h, NROWS);

    // ---- layer-0 SpMM y-part (needs permute B) ----
    cudaStreamWaitEvent(0, g_evB, 0);
    spmm256_part<<<(MROWS + 7) / 8, T>>>(rp + RP_HT,  pack + CS_HT,
                                         rp + RP_HTH, pack + CS_HTH,
                                         xw0, yw0, y1h, MROWS);

    // ---- layer-1 GEMMs (fp16 A mma) ----
    {
        int nb1 = (NROWS + 63) / 64, nb2 = (MROWS + 63) / 64;
        dim3 g(64 / 64, nb1 + nb2);
        gemm2_mma<1><<<g, T>>>(x1h, NROWS, y1h, MROWS, W1, x1w1, y1w1, 64, nb1);
    }

    // ---- layer-1 SpMM (combined, 2 nnz/warp) straight into d_out ----
    spmm64_all<<<(NROWS + MROWS + 7) / 8, T>>>(rp, pack, x1w1, y1w1, out);
}

// round 14
// speedup vs baseline: 1.0526x; 1.0091x over previous
#include <cuda_runtime.h>
#include <cuda_fp16.h>
#include <cstdint>

// ---------------- problem constants ----------------
#define NROWS 50000
#define MROWS 20000
#define NNZ_HHT 1600000
#define NNZ_H   1000000
#define NNZ_HT  1000000
#define NNZ_HTH 640000
#define NNZ_TOT (NNZ_HHT + NNZ_H + NNZ_HT + NNZ_HTH)
#define NEG_SLOPE 0.2f

// ---------------- half scratch (element counts) ----------------
#define H_XW0   0L
#define H_YW0   (H_XW0  + 12800000L)
#define H_X1    (H_YW0  + 5120000L)
#define H_Y1    (H_X1   + 12800000L)
#define H_X1W1  (H_Y1   + 5120000L)
#define H_Y1W1  (H_X1W1 + 3200000L)
#define HS_TOT  (H_Y1W1 + 1280000L)

// ---------------- int scratch ----------------
#define I_CUR   0L
#define I_RP    (I_CUR + 2L*NROWS + 2L*MROWS)
#define IS_TOT  (I_RP  + 2L*(NROWS+1) + 2L*(MROWS+1))

#define CUR_HHT 0L
#define CUR_H   ((long)NROWS)
#define CUR_HT  (2L*NROWS)
#define CUR_HTH (2L*NROWS + MROWS)
#define RP_HHT  0L
#define RP_H    ((long)NROWS + 1)
#define RP_HT   (2L*(NROWS + 1))
#define RP_HTH  (2L*(NROWS + 1) + MROWS + 1)
#define CS_HHT  0L
#define CS_H    ((long)NNZ_HHT)
#define CS_HT   ((long)NNZ_HHT + NNZ_H)
#define CS_HTH  ((long)NNZ_HHT + NNZ_H + NNZ_HT)

__device__ __align__(16) __half g_hs[HS_TOT];
__device__ __align__(16) int    g_is[IS_TOT];
__device__ __align__(16) int2   g_pack[NNZ_TOT];

__device__ __forceinline__ float leaky(float v) {
    return v >= 0.f ? v : NEG_SLOPE * v;
}

// ---------------- CSR build: count ----------------
__global__ void count_all_k(const int* __restrict__ r0, const int* __restrict__ r1,
                            const int* __restrict__ r2, const int* __restrict__ r3,
                            int* __restrict__ cur) {
    long i = (long)blockIdx.x * blockDim.x + threadIdx.x;
    if (i >= NNZ_TOT) return;
    if (i < NNZ_HHT) {
        atomicAdd(&cur[CUR_HHT + r0[i]], 1);
    } else if (i < NNZ_HHT + NNZ_H) {
        atomicAdd(&cur[CUR_H + r1[i - NNZ_HHT]], 1);
    } else if (i < NNZ_HHT + NNZ_H + NNZ_HT) {
        atomicAdd(&cur[CUR_HT + r2[i - NNZ_HHT - NNZ_H]], 1);
    } else {
        atomicAdd(&cur[CUR_HTH + r3[i - NNZ_HHT - NNZ_H - NNZ_HT]], 1);
    }
}

// ---------------- CSR build: fast single-pass scan (4 blocks) ----------------
__global__ void scan_all_k(int* __restrict__ cur, int* __restrict__ rp) {
    __shared__ int wsum[32];
    int b = blockIdx.x;
    int n; int* cnt; int* rowp;
    if (b == 0)      { n = NROWS; cnt = cur + CUR_HHT; rowp = rp + RP_HHT; }
    else if (b == 1) { n = NROWS; cnt = cur + CUR_H;   rowp = rp + RP_H;   }
    else if (b == 2) { n = MROWS; cnt = cur + CUR_HT;  rowp = rp + RP_HT;  }
    else             { n = MROWS; cnt = cur + CUR_HTH; rowp = rp + RP_HTH; }

    int t = threadIdx.x;            // 1024 threads
    int lane = t & 31, wid = t >> 5;
    int CH = (n + 1023) >> 10;
    int s0 = t * CH; if (s0 > n) s0 = n;
    int s1 = s0 + CH; if (s1 > n) s1 = n;

    int sum = 0;
    for (int i = s0; i < s1; i++) sum += cnt[i];

    int v = sum;
    #pragma unroll
    for (int o = 1; o < 32; o <<= 1) {
        int u = __shfl_up_sync(0xffffffffu, v, o);
        if (lane >= o) v += u;
    }
    if (lane == 31) wsum[wid] = v;
    __syncthreads();
    if (wid == 0) {
        int w = wsum[lane];
        #pragma unroll
        for (int o = 1; o < 32; o <<= 1) {
            int u = __shfl_up_sync(0xffffffffu, w, o);
            if (lane >= o) w += u;
        }
        wsum[lane] = w;
    }
    __syncthreads();
    int excl = v - sum + (wid ? wsum[wid - 1] : 0);

    int run = excl;
    for (int i = s0; i < s1; i++) {
        int c = cnt[i];
        rowp[i] = run;
        cnt[i] = run;
        run += c;
    }
    if (t == 1023) rowp[n] = run;
}

// ---------------- CSR build: permute over a range, ILP=2 ----------------
struct Ent { int r, c; float v; long cs; int* cu; };

__device__ __forceinline__ Ent load_ent(long i,
    const int* r0, const int* c0, const float* v0,
    const int* r1, const int* c1, const float* v1,
    const int* r2, const int* c2, const float* v2,
    const int* r3, const int* c3, const float* v3, int* cur) {
    Ent e;
    if (i < NNZ_HHT) {
        e.r = r0[i]; e.c = c0[i]; e.v = v0[i]; e.cs = CS_HHT; e.cu = cur + CUR_HHT;
    } else if (i < NNZ_HHT + NNZ_H) {
        long j = i - NNZ_HHT;
        e.r = r1[j]; e.c = c1[j]; e.v = v1[j]; e.cs = CS_H; e.cu = cur + CUR_H;
    } else if (i < NNZ_HHT + NNZ_H + NNZ_HT) {
        long j = i - NNZ_HHT - NNZ_H;
        e.r = r2[j]; e.c = c2[j]; e.v = v2[j]; e.cs = CS_HT; e.cu = cur + CUR_HT;
    } else {
        long j = i - NNZ_HHT - NNZ_H - NNZ_HT;
        e.r = r3[j]; e.c = c3[j]; e.v = v3[j]; e.cs = CS_HTH; e.cu = cur + CUR_HTH;
    }
    return e;
}

__global__ void permute_range_k(const int* __restrict__ r0, const int* __restrict__ c0, const float* __restrict__ v0,
                                const int* __restrict__ r1, const int* __restrict__ c1, const float* __restrict__ v1,
                                const int* __restrict__ r2, const int* __restrict__ c2, const float* __restrict__ v2,
                                const int* __restrict__ r3, const int* __restrict__ c3, const float* __restrict__ v3,
                                int* __restrict__ cur, int2* __restrict__ pack,
                                long start, long end) {
    long i = start + ((long)blockIdx.x * blockDim.x + threadIdx.x) * 2;
    if (i >= end) return;
    Ent e0 = load_ent(i, r0,c0,v0, r1,c1,v1, r2,c2,v2, r3,c3,v3, cur);
    bool two = (i + 1 < end);
    Ent e1;
    if (two) e1 = load_ent(i + 1, r0,c0,v0, r1,c1,v1, r2,c2,v2, r3,c3,v3, cur);
    int s0 = atomicAdd(&e0.cu[e0.r], 1);
    pack[e0.cs + s0] = make_int2(e0.c, __float_as_int(e0.v));
    if (two) {
        int s1 = atomicAdd(&e1.cu[e1.r], 1);
        pack[e1.cs + s1] = make_int2(e1.c, __float_as_int(e1.v));
    }
}

// ---------------- tensor-core GEMM: C[Rows,Ncols] = A @ W,  K=256 ----------------
__device__ __forceinline__ void mma16816(float* c, const unsigned* a, const unsigned* b) {
    asm volatile("mma.sync.aligned.m16n8k16.row.col.f32.f16.f16.f32 "
                 "{%0,%1,%2,%3}, {%4,%5,%6,%7}, {%8,%9}, {%0,%1,%2,%3};"
                 : "+f"(c[0]), "+f"(c[1]), "+f"(c[2]), "+f"(c[3])
                 : "r"(a[0]), "r"(a[1]), "r"(a[2]), "r"(a[3]),
                   "r"(b[0]), "r"(b[1]));
}

template<int AHALF>
__global__ void gemm2_mma(const void* __restrict__ A1v, int Rows1,
                          const void* __restrict__ A2v, int Rows2,
                          const float* __restrict__ W,
                          __half* __restrict__ C1, __half* __restrict__ C2,
                          int Ncols, int nb1) {
    const int BK = 32;
    __shared__ __align__(16) __half As[64][40];
    __shared__ __align__(16) __half Bs[64][40];

    const void* Av;
    __half* C;
    int Rows, m0;
    if ((int)blockIdx.y < nb1) { Av = A1v; C = C1; Rows = Rows1; m0 = blockIdx.y * 64; }
    else                        { Av = A2v; C = C2; Rows = Rows2; m0 = (blockIdx.y - nb1) * 64; }

    int tid = threadIdx.x;
    int lane = tid & 31, warp = tid >> 5;
    int wm = warp >> 2;
    int wn = warp & 3;
    int n0 = blockIdx.x * 64;

    float c[2][2][4] = {};

    for (int k0 = 0; k0 < 256; k0 += BK) {
        {
            int m  = tid >> 2;
            int kc = (tid & 3) * 8;
            int gm = m0 + m;
            __half h[8];
            if (gm < Rows) {
                if (AHALF) {
                    const __half* A = (const __half*)Av;
                    *(uint4*)h = *(const uint4*)(A + (long)gm * 256 + k0 + kc);
                } else {
                    const float* A = (const float*)Av;
                    float4 f0 = *(const float4*)(A + (long)gm * 256 + k0 + kc);
                    float4 f1 = *(const float4*)(A + (long)gm * 256 + k0 + kc + 4);
                    h[0] = __float2half(f0.x); h[1] = __float2half(f0.y);
                    h[2] = __float2half(f0.z); h[3] = __float2half(f0.w);
                    h[4] = __float2half(f1.x); h[5] = __float2half(f1.y);
                    h[6] = __float2half(f1.z); h[7] = __float2half(f1.w);
                }
            } else {
                #pragma unroll
                for (int q = 0; q < 8; q++) h[q] = __float2half(0.f);
            }
            *(uint4*)&As[m][kc] = *(uint4*)h;
        }
        {
            int n  = tid & 63;
            int k8 = (tid >> 6) * 8;
            #pragma unroll
            for (int q = 0; q < 8; q++) {
                float w = W[(long)(k0 + k8 + q) * Ncols + n0 + n];
                Bs[n][k8 + q] = __float2half(w);
            }
        }
        __syncthreads();

        #pragma unroll
        for (int ks = 0; ks < 2; ks++) {
            int kk = ks * 16;
            int gr = lane >> 2;
            int gk = (lane & 3) * 2;
            unsigned bf[2][2];
            #pragma unroll
            for (int j = 0; j < 2; j++) {
                int nn = wn * 16 + j * 8 + gr;
                bf[j][0] = *(const unsigned*)&Bs[nn][kk + gk];
                bf[j][1] = *(const unsigned*)&Bs[nn][kk + gk + 8];
            }
            #pragma unroll
            for (int i = 0; i < 2; i++) {
                int r = wm * 32 + i * 16 + gr;
                unsigned a[4];
                a[0] = *(const unsigned*)&As[r][kk + gk];
                a[1] = *(const unsigned*)&As[r + 8][kk + gk];
                a[2] = *(const unsigned*)&As[r][kk + gk + 8];
                a[3] = *(const unsigned*)&As[r + 8][kk + gk + 8];
                mma16816(c[i][0], a, bf[0]);
                mma16816(c[i][1], a, bf[1]);
            }
        }
        __syncthreads();
    }

    int gr = lane >> 2;
    int gc = (lane & 3) * 2;
    #pragma unroll
    for (int i = 0; i < 2; i++) {
        #pragma unroll
        for (int j = 0; j < 2; j++) {
            int rg = m0 + wm * 32 + i * 16 + gr;
            int cg = n0 + wn * 16 + j * 8 + gc;
            if (rg < Rows) {
                __half2 h = __floats2half2_rn(c[i][j][0], c[i][j][1]);
                *(__half2*)(C + (long)rg * Ncols + cg) = h;
            }
            if (rg + 8 < Rows) {
                __half2 h = __floats2half2_rn(c[i][j][2], c[i][j][3]);
                *(__half2*)(C + (long)(rg + 8) * Ncols + cg) = h;
            }
        }
    }
}

// ---------------- F=256 gather accumulate, MLP=4 (R8/R12-proven) ----------------
__device__ __forceinline__ void macc8(float* acc, float4 raw, float v) {
    const __half2* h = (const __half2*)&raw;
    #pragma unroll
    for (int q = 0; q < 4; q++) {
        float2 f = __half22float2(h[q]);
        acc[q * 2 + 0] += v * f.x;
        acc[q * 2 + 1] += v * f.y;
    }
}

__device__ __forceinline__ void accum256(const int2* __restrict__ pack,
                                         int s, int e, const __half* __restrict__ dense,
                                         int lane, float* acc) {
    int j = s;
    if (j + 4 <= e) {
        int2 p0 = __ldg(pack + j),     p1 = __ldg(pack + j + 1);
        int2 p2 = __ldg(pack + j + 2), p3 = __ldg(pack + j + 3);
        for (; j + 4 <= e; ) {
            float4 r0 = ((const float4*)(dense + (long)p0.x * 256))[lane];
            float4 r1 = ((const float4*)(dense + (long)p1.x * 256))[lane];
            float4 r2 = ((const float4*)(dense + (long)p2.x * 256))[lane];
            float4 r3 = ((const float4*)(dense + (long)p3.x * 256))[lane];
            float w0 = __int_as_float(p0.y), w1 = __int_as_float(p1.y);
            float w2 = __int_as_float(p2.y), w3 = __int_as_float(p3.y);
            j += 4;
            if (j + 4 <= e) {
                p0 = __ldg(pack + j);     p1 = __ldg(pack + j + 1);
                p2 = __ldg(pack + j + 2); p3 = __ldg(pack + j + 3);
            }
            macc8(acc, r0, w0);
            macc8(acc, r1, w1);
            macc8(acc, r2, w2);
            macc8(acc, r3, w3);
        }
    }
    for (; j < e; j++) {
        int2 p = __ldg(pack + j);
        float4 r = ((const float4*)(dense + (long)p.x * 256))[lane];
        macc8(acc, r, __int_as_float(p.y));
    }
}

// ---------------- F=256 dual SpMM + leaky over a row range -> fp16 ----------------
__global__ void spmm256_part(const int* __restrict__ rpA, const int2* __restrict__ packA,
                             const int* __restrict__ rpB, const int2* __restrict__ packB,
                             const __half* __restrict__ dA, const __half* __restrict__ dB,
                             __half* __restrict__ outp, int nrows) {
    int r = (blockIdx.x * blockDim.x + threadIdx.x) >> 5;
    if (r >= nrows) return;
    int lane = threadIdx.x & 31;

    float a[8] = {}, b[8] = {};
    accum256(packA, rpA[r], rpA[r + 1], dA, lane, a);
    accum256(packB, rpB[r], rpB[r + 1], dB, lane, b);

    __half2 h[4];
    #pragma unroll
    for (int q = 0; q < 4; q++)
        h[q] = __floats2half2_rn(leaky(a[q * 2]) + leaky(b[q * 2]),
                                 leaky(a[q * 2 + 1]) + leaky(b[q * 2 + 1]));
    uint4 u;
    u.x = *(unsigned*)&h[0]; u.y = *(unsigned*)&h[1];
    u.z = *(unsigned*)&h[2]; u.w = *(unsigned*)&h[3];
    *((uint4*)(outp + (long)r * 256) + lane) = u;
}

// ---------------- F=64 gather, 2 nnz per warp (half-warp per nnz) ----------------
__device__ __forceinline__ void vmacc4(float4& acc, uint2 d, float v) {
    float2 f0 = __half22float2(*(__half2*)&d.x);
    float2 f1 = __half22float2(*(__half2*)&d.y);
    acc.x += v * f0.x; acc.y += v * f0.y;
    acc.z += v * f1.x; acc.w += v * f1.y;
}

__device__ __forceinline__ void accum64v(const int2* __restrict__ pack,
                                         int s, int e, const __half* __restrict__ dense,
                                         int sub, int fl, float4& acc) {
    int j = s;
    for (; j + 4 <= e; j += 4) {
        int2 p0 = __ldg(pack + j + sub);
        int2 p1 = __ldg(pack + j + 2 + sub);
        uint2 d0 = *(const uint2*)(dense + (long)p0.x * 64 + fl * 4);
        uint2 d1 = *(const uint2*)(dense + (long)p1.x * 64 + fl * 4);
        vmacc4(acc, d0, __int_as_float(p0.y));
        vmacc4(acc, d1, __int_as_float(p1.y));
    }
    for (; j + 2 <= e; j += 2) {
        int2 p = __ldg(pack + j + sub);
        uint2 d = *(const uint2*)(dense + (long)p.x * 64 + fl * 4);
        vmacc4(acc, d, __int_as_float(p.y));
    }
    if (j < e) {
        int2 p = __ldg(pack + j);
        uint2 d = *(const uint2*)(dense + (long)p.x * 64 + fl * 4);
        float v = (sub == 0) ? __int_as_float(p.y) : 0.f;
        vmacc4(acc, d, v);
    }
}

__global__ void spmm64_all(const int* __restrict__ rp, const int2* __restrict__ pack,
                           const __half* __restrict__ dX, const __half* __restrict__ dY,
                           float* __restrict__ outbase) {
    int w = (blockIdx.x * blockDim.x + threadIdx.x) >> 5;
    if (w >= NROWS + MROWS) return;
    int lane = threadIdx.x & 31;
    int sub = lane >> 4;
    int fl  = lane & 15;

    const int* rpA; const int* rpB; long csA, csB; int r;
    if (w < NROWS) {
        r = w;
        rpA = rp + RP_HHT; csA = CS_HHT;
        rpB = rp + RP_H;   csB = CS_H;
    } else {
        r = w - NROWS;
        rpA = rp + RP_HT;  csA = CS_HT;
        rpB = rp + RP_HTH; csB = CS_HTH;
    }

    float4 a = make_float4(0, 0, 0, 0), b = a;
    accum64v(pack + csA, rpA[r], rpA[r + 1], dX, sub, fl, a);
    accum64v(pack + csB, rpB[r], rpB[r + 1], dY, sub, fl, b);

    a.x += __shfl_down_sync(0xffffffffu, a.x, 16);
    a.y += __shfl_down_sync(0xffffffffu, a.y, 16);
    a.z += __shfl_down_sync(0xffffffffu, a.z, 16);
    a.w += __shfl_down_sync(0xffffffffu, a.w, 16);
    b.x += __shfl_down_sync(0xffffffffu, b.x, 16);
    b.y += __shfl_down_sync(0xffffffffu, b.y, 16);
    b.z += __shfl_down_sync(0xffffffffu, b.z, 16);
    b.w += __shfl_down_sync(0xffffffffu, b.w, 16);

    if (sub == 0) {
        float4 res;
        res.x = leaky(a.x) + leaky(b.x);
        res.y = leaky(a.y) + leaky(b.y);
        res.z = leaky(a.z) + leaky(b.z);
        res.w = leaky(a.w) + leaky(b.w);
        ((float4*)(outbase + (long)w * 64))[fl] = res;
    }
}

// ---------------- side-stream handles ----------------
static cudaStream_t g_side = nullptr;
static cudaEvent_t  g_fork = nullptr;
static cudaEvent_t  g_evA = nullptr;
static cudaEvent_t  g_evB = nullptr;
static cudaEvent_t  g_evX = nullptr;
static cudaEvent_t  g_evG = nullptr;

extern "C" void kernel_launch(void* const* d_in, const int* in_sizes, int n_in,
                              void* d_out, int out_size) {
    const float* x  = (const float*)d_in[0];
    const float* y  = (const float*)d_in[1];
    const float* W0 = (const float*)d_in[2];
    const float* W1 = (const float*)d_in[3];
    const int*   hht_r = (const int*)d_in[4];
    const int*   hht_c = (const int*)d_in[5];
    const float* hht_v = (const float*)d_in[6];
    const int*   h_r = (const int*)d_in[7];
    const int*   h_c = (const int*)d_in[8];
    const float* h_v = (const float*)d_in[9];
    const int*   ht_r = (const int*)d_in[10];
    const int*   ht_c = (const int*)d_in[11];
    const float* ht_v = (const float*)d_in[12];
    const int*   hth_r = (const int*)d_in[13];
    const int*   hth_c = (const int*)d_in[14];
    const float* hth_v = (const float*)d_in[15];
    float* out = (float*)d_out;

    if (!g_side) {
        cudaStreamCreateWithFlags(&g_side, cudaStreamNonBlocking);
        cudaEventCreateWithFlags(&g_fork, cudaEventDisableTiming);
        cudaEventCreateWithFlags(&g_evA, cudaEventDisableTiming);
        cudaEventCreateWithFlags(&g_evB, cudaEventDisableTiming);
        cudaEventCreateWithFlags(&g_evX, cudaEventDisableTiming);
        cudaEventCreateWithFlags(&g_evG, cudaEventDisableTiming);
    }

    void* p = nullptr;
    cudaGetSymbolAddress(&p, g_hs);
    __half* H = (__half*)p;
    cudaGetSymbolAddress(&p, g_is);
    int* I = (int*)p;
    cudaGetSymbolAddress(&p, g_pack);
    int2* pack = (int2*)p;

    __half* xw0  = H + H_XW0;
    __half* yw0  = H + H_YW0;
    __half* x1h  = H + H_X1;
    __half* y1h  = H + H_Y1;
    __half* x1w1 = H + H_X1W1;
    __half* y1w1 = H + H_Y1W1;

    int* cur = I + I_CUR;
    int* rp  = I + I_RP;

    const int T = 256;
    const long SPLIT = (long)NNZ_HHT + NNZ_H;   // x-rows use HHT+H; y-rows use HT+HTH
    int nbx = (NROWS + 63) / 64, nby = (MROWS + 63) / 64;

    // ---- fork: CSR build on side stream, layer-0 GEMM on main stream ----
    cudaEventRecord(g_fork, 0);
    cudaStreamWaitEvent(g_side, g_fork, 0);

    // side stream: CSR build part A (zero via memset node, count, scan, permute A)
    {
        int ncur = 2 * NROWS + 2 * MROWS;
        cudaMemsetAsync(cur, 0, (size_t)ncur * sizeof(int), g_side);
        count_all_k<<<(NNZ_TOT + T - 1) / T, T, 0, g_side>>>(hht_r, h_r, ht_r, hth_r, cur);
        scan_all_k<<<4, 1024, 0, g_side>>>(cur, rp);
        permute_range_k<<<(int)((SPLIT / 2 + T - 1) / T), T, 0, g_side>>>(
            hht_r, hht_c, hht_v, h_r, h_c, h_v, ht_r, ht_c, ht_v,
            hth_r, hth_c, hth_v, cur, pack, 0L, SPLIT);
        cudaEventRecord(g_evA, g_side);
    }

    // main stream: layer-0 GEMMs (fp32 A -> fp16 mma)
    {
        dim3 g(256 / 64, nbx + nby);
        gemm2_mma<0><<<g, T>>>(x, NROWS, y, MROWS, W0, xw0, yw0, 256, nbx);
    }

    // main: layer-0 SpMM x-part (needs permute A only) — submitted early so ncu
    // (-s 5) captures it; permB below still executes concurrently on side stream.
    cudaStreamWaitEvent(0, g_evA, 0);
    spmm256_part<<<(NROWS + 7) / 8, T>>>(rp + RP_HHT, pack + CS_HHT,
                                         rp + RP_H,   pack + CS_H,
                                         xw0, yw0, x1h, NROWS);
    cudaEventRecord(g_evX, 0);

    // side stream: permute B (runs right after permute A, overlapping spmm256x)
    permute_range_k<<<(int)(((NNZ_TOT - SPLIT) / 2 + T - 1) / T), T, 0, g_side>>>(
        hht_r, hht_c, hht_v, h_r, h_c, h_v, ht_r, ht_c, ht_v,
        hth_r, hth_c, hth_v, cur, pack, SPLIT, (long)NNZ_TOT);
    cudaEventRecord(g_evB, g_side);

    // side stream: gemm1 x-part (needs x1h) — overlaps spmm256 y-part on main
    cudaStreamWaitEvent(g_side, g_evX, 0);
    {
        dim3 g(1, nbx);
        gemm2_mma<1><<<g, T, 0, g_side>>>(x1h, NROWS, x1h, 0, W1, x1w1, x1w1, 64, nbx);
    }
    cudaEventRecord(g_evG, g_side);

    // main: layer-0 SpMM y-part (needs permute B)
    cudaStreamWaitEvent(0, g_evB, 0);
    spmm256_part<<<(MROWS + 7) / 8, T>>>(rp + RP_HT,  pack + CS_HT,
                                         rp + RP_HTH, pack + CS_HTH,
                                         xw0, yw0, y1h, MROWS);

    // main: gemm1 y-part
    {
        dim3 g(1, nby);
        gemm2_mma<1><<<g, T>>>(y1h, MROWS, y1h, 0, W1, y1w1, y1w1, 64, nby);
    }

    // main: layer-1 SpMM (combined) straight into d_out — needs both gemm1 parts
    cudaStreamWaitEvent(0, g_evG, 0);
    spmm64_all<<<(NROWS + MROWS + 7) / 8, T>>>(rp, pack, x1w1, y1w1, out);
}

// round 15
// speedup vs baseline: 1.1071x; 1.0517x over previous
#include <cuda_runtime.h>
#include <cuda_fp16.h>
#include <cstdint>

// ---------------- problem constants ----------------
#define NROWS 50000
#define MROWS 20000
#define NNZ_HHT 1600000
#define NNZ_H   1000000
#define NNZ_HT  1000000
#define NNZ_HTH 640000
#define NNZ_TOT (NNZ_HHT + NNZ_H + NNZ_HT + NNZ_HTH)
#define NEG_SLOPE 0.2f

// ---------------- half scratch (element counts) ----------------
#define H_XW0   0L
#define H_YW0   (H_XW0  + 12800000L)
#define H_X1    (H_YW0  + 5120000L)
#define H_Y1    (H_X1   + 12800000L)
#define H_X1W1  (H_Y1   + 5120000L)
#define H_Y1W1  (H_X1W1 + 3200000L)
#define HS_TOT  (H_Y1W1 + 1280000L)

// ---------------- int scratch ----------------
#define I_CUR   0L
#define I_RP    (I_CUR + 2L*NROWS + 2L*MROWS)
#define IS_TOT  (I_RP  + 2L*(NROWS+1) + 2L*(MROWS+1))

#define CUR_HHT 0L
#define CUR_H   ((long)NROWS)
#define CUR_HT  (2L*NROWS)
#define CUR_HTH (2L*NROWS + MROWS)
#define RP_HHT  0L
#define RP_H    ((long)NROWS + 1)
#define RP_HT   (2L*(NROWS + 1))
#define RP_HTH  (2L*(NROWS + 1) + MROWS + 1)
#define CS_HHT  0L
#define CS_H    ((long)NNZ_HHT)
#define CS_HT   ((long)NNZ_HHT + NNZ_H)
#define CS_HTH  ((long)NNZ_HHT + NNZ_H + NNZ_HT)

__device__ __align__(16) __half g_hs[HS_TOT];
__device__ __align__(16) int    g_is[IS_TOT];
__device__ __align__(16) int2   g_pack[NNZ_TOT];

__device__ __forceinline__ float leaky(float v) {
    return v >= 0.f ? v : NEG_SLOPE * v;
}

// ---------------- CSR build: count ----------------
__global__ void count_all_k(const int* __restrict__ r0, const int* __restrict__ r1,
                            const int* __restrict__ r2, const int* __restrict__ r3,
                            int* __restrict__ cur) {
    long i = (long)blockIdx.x * blockDim.x + threadIdx.x;
    if (i >= NNZ_TOT) return;
    if (i < NNZ_HHT) {
        atomicAdd(&cur[CUR_HHT + r0[i]], 1);
    } else if (i < NNZ_HHT + NNZ_H) {
        atomicAdd(&cur[CUR_H + r1[i - NNZ_HHT]], 1);
    } else if (i < NNZ_HHT + NNZ_H + NNZ_HT) {
        atomicAdd(&cur[CUR_HT + r2[i - NNZ_HHT - NNZ_H]], 1);
    } else {
        atomicAdd(&cur[CUR_HTH + r3[i - NNZ_HHT - NNZ_H - NNZ_HT]], 1);
    }
}

// ---------------- CSR build: fast single-pass scan (4 blocks) ----------------
__global__ void scan_all_k(int* __restrict__ cur, int* __restrict__ rp) {
    __shared__ int wsum[32];
    int b = blockIdx.x;
    int n; int* cnt; int* rowp;
    if (b == 0)      { n = NROWS; cnt = cur + CUR_HHT; rowp = rp + RP_HHT; }
    else if (b == 1) { n = NROWS; cnt = cur + CUR_H;   rowp = rp + RP_H;   }
    else if (b == 2) { n = MROWS; cnt = cur + CUR_HT;  rowp = rp + RP_HT;  }
    else             { n = MROWS; cnt = cur + CUR_HTH; rowp = rp + RP_HTH; }

    int t = threadIdx.x;            // 1024 threads
    int lane = t & 31, wid = t >> 5;
    int CH = (n + 1023) >> 10;
    int s0 = t * CH; if (s0 > n) s0 = n;
    int s1 = s0 + CH; if (s1 > n) s1 = n;

    int sum = 0;
    for (int i = s0; i < s1; i++) sum += cnt[i];

    int v = sum;
    #pragma unroll
    for (int o = 1; o < 32; o <<= 1) {
        int u = __shfl_up_sync(0xffffffffu, v, o);
        if (lane >= o) v += u;
    }
    if (lane == 31) wsum[wid] = v;
    __syncthreads();
    if (wid == 0) {
        int w = wsum[lane];
        #pragma unroll
        for (int o = 1; o < 32; o <<= 1) {
            int u = __shfl_up_sync(0xffffffffu, w, o);
            if (lane >= o) w += u;
        }
        wsum[lane] = w;
    }
    __syncthreads();
    int excl = v - sum + (wid ? wsum[wid - 1] : 0);

    int run = excl;
    for (int i = s0; i < s1; i++) {
        int c = cnt[i];
        rowp[i] = run;
        cnt[i] = run;
        run += c;
    }
    if (t == 1023) rowp[n] = run;
}

// ---------------- CSR build: permute over a range, ILP=2 ----------------
struct Ent { int r, c; float v; long cs; int* cu; };

__device__ __forceinline__ Ent load_ent(long i,
    const int* r0, const int* c0, const float* v0,
    const int* r1, const int* c1, const float* v1,
    const int* r2, const int* c2, const float* v2,
    const int* r3, const int* c3, const float* v3, int* cur) {
    Ent e;
    if (i < NNZ_HHT) {
        e.r = r0[i]; e.c = c0[i]; e.v = v0[i]; e.cs = CS_HHT; e.cu = cur + CUR_HHT;
    } else if (i < NNZ_HHT + NNZ_H) {
        long j = i - NNZ_HHT;
        e.r = r1[j]; e.c = c1[j]; e.v = v1[j]; e.cs = CS_H; e.cu = cur + CUR_H;
    } else if (i < NNZ_HHT + NNZ_H + NNZ_HT) {
        long j = i - NNZ_HHT - NNZ_H;
        e.r = r2[j]; e.c = c2[j]; e.v = v2[j]; e.cs = CS_HT; e.cu = cur + CUR_HT;
    } else {
        long j = i - NNZ_HHT - NNZ_H - NNZ_HT;
        e.r = r3[j]; e.c = c3[j]; e.v = v3[j]; e.cs = CS_HTH; e.cu = cur + CUR_HTH;
    }
    return e;
}

__global__ void permute_range_k(const int* __restrict__ r0, const int* __restrict__ c0, const float* __restrict__ v0,
                                const int* __restrict__ r1, const int* __restrict__ c1, const float* __restrict__ v1,
                                const int* __restrict__ r2, const int* __restrict__ c2, const float* __restrict__ v2,
                                const int* __restrict__ r3, const int* __restrict__ c3, const float* __restrict__ v3,
                                int* __restrict__ cur, int2* __restrict__ pack,
                                long start, long end) {
    long i = start + ((long)blockIdx.x * blockDim.x + threadIdx.x) * 2;
    if (i >= end) return;
    Ent e0 = load_ent(i, r0,c0,v0, r1,c1,v1, r2,c2,v2, r3,c3,v3, cur);
    bool two = (i + 1 < end);
    Ent e1;
    if (two) e1 = load_ent(i + 1, r0,c0,v0, r1,c1,v1, r2,c2,v2, r3,c3,v3, cur);
    int s0 = atomicAdd(&e0.cu[e0.r], 1);
    pack[e0.cs + s0] = make_int2(e0.c, __float_as_int(e0.v));
    if (two) {
        int s1 = atomicAdd(&e1.cu[e1.r], 1);
        pack[e1.cs + s1] = make_int2(e1.c, __float_as_int(e1.v));
    }
}

// ---------------- mma primitive ----------------
__device__ __forceinline__ void mma16816(float* c, const unsigned* a, const unsigned* b) {
    asm volatile("mma.sync.aligned.m16n8k16.row.col.f32.f16.f16.f32 "
                 "{%0,%1,%2,%3}, {%4,%5,%6,%7}, {%8,%9}, {%0,%1,%2,%3};"
                 : "+f"(c[0]), "+f"(c[1]), "+f"(c[2]), "+f"(c[3])
                 : "r"(a[0]), "r"(a[1]), "r"(a[2]), "r"(a[3]),
                   "r"(b[0]), "r"(b[1]));
}

// ---------------- layer-0 GEMM: 128x128 tiles, Ncols=256, fp32 A -> fp16 C ----------------
__global__ void gemm0_mma(const float* __restrict__ A1, int Rows1,
                          const float* __restrict__ A2, int Rows2,
                          const float* __restrict__ W,
                          __half* __restrict__ C1, __half* __restrict__ C2,
                          int nb1) {
    const int BK = 32;
    __shared__ __align__(16) __half As[128][40];   // 10 KB
    __shared__ __align__(16) __half Bs[128][40];   // 10 KB  (Bs[n][k])

    const float* A;
    __half* C;
    int Rows, m0;
    if ((int)blockIdx.y < nb1) { A = A1; C = C1; Rows = Rows1; m0 = blockIdx.y * 128; }
    else                        { A = A2; C = C2; Rows = Rows2; m0 = (blockIdx.y - nb1) * 128; }

    int tid = threadIdx.x;        // 256
    int lane = tid & 31, warp = tid >> 5;
    int wm = warp >> 2;           // 0..1 -> 64 rows each
    int wn = warp & 3;            // 0..3 -> 32 cols each
    int n0 = blockIdx.x * 128;

    float c[4][4][4] = {};

    for (int k0 = 0; k0 < 256; k0 += BK) {
        // --- A tile: 128 rows x 32 k (fp32 -> fp16 smem). 16 elems/thread. ---
        {
            int m  = tid >> 1;
            int kc = (tid & 1) * 16;
            __half h[16];
            if (m0 + m < Rows) {
                const float* src = A + (long)(m0 + m) * 256 + k0 + kc;
                #pragma unroll
                for (int q = 0; q < 4; q++) {
                    float4 f = *(const float4*)(src + q * 4);
                    h[q * 4 + 0] = __float2half(f.x);
                    h[q * 4 + 1] = __float2half(f.y);
                    h[q * 4 + 2] = __float2half(f.z);
                    h[q * 4 + 3] = __float2half(f.w);
                }
            } else {
                #pragma unroll
                for (int q = 0; q < 16; q++) h[q] = __float2half(0.f);
            }
            *(uint4*)&As[m][kc]     = *(uint4*)&h[0];
            *(uint4*)&As[m][kc + 8] = *(uint4*)&h[8];
        }
        // --- W tile: 32 k x 128 n, transposed into Bs[n][k]. 16 elems/thread. ---
        {
            int n  = tid & 127;
            int kb = (tid >> 7) * 16;   // 0 or 16
            __half h[16];
            #pragma unroll
            for (int q = 0; q < 16; q++)
                h[q] = __float2half(W[(long)(k0 + kb + q) * 256 + n0 + n]);
            *(uint4*)&Bs[n][kb]     = *(uint4*)&h[0];
            *(uint4*)&Bs[n][kb + 8] = *(uint4*)&h[8];
        }
        __syncthreads();

        #pragma unroll
        for (int ks = 0; ks < 2; ks++) {
            int kk = ks * 16;
            int gr = lane >> 2;
            int gk = (lane & 3) * 2;
            unsigned bf[4][2];
            #pragma unroll
            for (int j = 0; j < 4; j++) {
                int nn = wn * 32 + j * 8 + gr;
                bf[j][0] = *(const unsigned*)&Bs[nn][kk + gk];
                bf[j][1] = *(const unsigned*)&Bs[nn][kk + gk + 8];
            }
            #pragma unroll
            for (int i = 0; i < 4; i++) {
                int r = wm * 64 + i * 16 + gr;
                unsigned a[4];
                a[0] = *(const unsigned*)&As[r][kk + gk];
                a[1] = *(const unsigned*)&As[r + 8][kk + gk];
                a[2] = *(const unsigned*)&As[r][kk + gk + 8];
                a[3] = *(const unsigned*)&As[r + 8][kk + gk + 8];
                #pragma unroll
                for (int j = 0; j < 4; j++)
                    mma16816(c[i][j], a, bf[j]);
            }
        }
        __syncthreads();
    }

    // --- epilogue: fp32 acc -> fp16 store ---
    int gr = lane >> 2;
    int gc = (lane & 3) * 2;
    #pragma unroll
    for (int i = 0; i < 4; i++) {
        #pragma unroll
        for (int j = 0; j < 4; j++) {
            int rg = m0 + wm * 64 + i * 16 + gr;
            int cg = n0 + wn * 32 + j * 8 + gc;
            if (rg < Rows) {
                __half2 h = __floats2half2_rn(c[i][j][0], c[i][j][1]);
                *(__half2*)(C + (long)rg * 256 + cg) = h;
            }
            if (rg + 8 < Rows) {
                __half2 h = __floats2half2_rn(c[i][j][2], c[i][j][3]);
                *(__half2*)(C + (long)(rg + 8) * 256 + cg) = h;
            }
        }
    }
}

// ---------------- layer-1 GEMM: 64x64 tiles, fp16 A, Ncols=64 ----------------
__global__ void gemm1_mma(const __half* __restrict__ A, int Rows,
                          const float* __restrict__ W,
                          __half* __restrict__ C) {
    const int BK = 32;
    __shared__ __align__(16) __half As[64][40];
    __shared__ __align__(16) __half Bs[64][40];

    int m0 = blockIdx.y * 64;
    int tid = threadIdx.x;
    int lane = tid & 31, warp = tid >> 5;
    int wm = warp >> 2;
    int wn = warp & 3;

    float c[2][2][4] = {};

    for (int k0 = 0; k0 < 256; k0 += BK) {
        {
            int m  = tid >> 2;
            int kc = (tid & 3) * 8;
            int gm = m0 + m;
            __half h[8];
            if (gm < Rows) {
                *(uint4*)h = *(const uint4*)(A + (long)gm * 256 + k0 + kc);
            } else {
                #pragma unroll
                for (int q = 0; q < 8; q++) h[q] = __float2half(0.f);
            }
            *(uint4*)&As[m][kc] = *(uint4*)h;
        }
        {
            int n  = tid & 63;
            int k8 = (tid >> 6) * 8;
            #pragma unroll
            for (int q = 0; q < 8; q++) {
                float w = W[(long)(k0 + k8 + q) * 64 + n];
                Bs[n][k8 + q] = __float2half(w);
            }
        }
        __syncthreads();

        #pragma unroll
        for (int ks = 0; ks < 2; ks++) {
            int kk = ks * 16;
            int gr = lane >> 2;
            int gk = (lane & 3) * 2;
            unsigned bf[2][2];
            #pragma unroll
            for (int j = 0; j < 2; j++) {
                int nn = wn * 16 + j * 8 + gr;
                bf[j][0] = *(const unsigned*)&Bs[nn][kk + gk];
                bf[j][1] = *(const unsigned*)&Bs[nn][kk + gk + 8];
            }
            #pragma unroll
            for (int i = 0; i < 2; i++) {
                int r = wm * 32 + i * 16 + gr;
                unsigned a[4];
                a[0] = *(const unsigned*)&As[r][kk + gk];
                a[1] = *(const unsigned*)&As[r + 8][kk + gk];
                a[2] = *(const unsigned*)&As[r][kk + gk + 8];
                a[3] = *(const unsigned*)&As[r + 8][kk + gk + 8];
                mma16816(c[i][0], a, bf[0]);
                mma16816(c[i][1], a, bf[1]);
            }
        }
        __syncthreads();
    }

    int gr = lane >> 2;
    int gc = (lane & 3) * 2;
    #pragma unroll
    for (int i = 0; i < 2; i++) {
        #pragma unroll
        for (int j = 0; j < 2; j++) {
            int rg = m0 + wm * 32 + i * 16 + gr;
            int cg = wn * 16 + j * 8 + gc;
            if (rg < Rows) {
                __half2 h = __floats2half2_rn(c[i][j][0], c[i][j][1]);
                *(__half2*)(C + (long)rg * 64 + cg) = h;
            }
            if (rg + 8 < Rows) {
                __half2 h = __floats2half2_rn(c[i][j][2], c[i][j][3]);
                *(__half2*)(C + (long)(rg + 8) * 64 + cg) = h;
            }
        }
    }
}

// ---------------- F=256 gather accumulate, MLP=4 ----------------
__device__ __forceinline__ void macc8(float* acc, float4 raw, float v) {
    const __half2* h = (const __half2*)&raw;
    #pragma unroll
    for (int q = 0; q < 4; q++) {
        float2 f = __half22float2(h[q]);
        acc[q * 2 + 0] += v * f.x;
        acc[q * 2 + 1] += v * f.y;
    }
}

__device__ __forceinline__ void accum256(const int2* __restrict__ pack,
                                         int s, int e, const __half* __restrict__ dense,
                                         int lane, float* acc) {
    int j = s;
    if (j + 4 <= e) {
        int2 p0 = __ldg(pack + j),     p1 = __ldg(pack + j + 1);
        int2 p2 = __ldg(pack + j + 2), p3 = __ldg(pack + j + 3);
        for (; j + 4 <= e; ) {
            float4 r0 = ((const float4*)(dense + (long)p0.x * 256))[lane];
            float4 r1 = ((const float4*)(dense + (long)p1.x * 256))[lane];
            float4 r2 = ((const float4*)(dense + (long)p2.x * 256))[lane];
            float4 r3 = ((const float4*)(dense + (long)p3.x * 256))[lane];
            float w0 = __int_as_float(p0.y), w1 = __int_as_float(p1.y);
            float w2 = __int_as_float(p2.y), w3 = __int_as_float(p3.y);
            j += 4;
            if (j + 4 <= e) {
                p0 = __ldg(pack + j);     p1 = __ldg(pack + j + 1);
                p2 = __ldg(pack + j + 2); p3 = __ldg(pack + j + 3);
            }
            macc8(acc, r0, w0);
            macc8(acc, r1, w1);
            macc8(acc, r2, w2);
            macc8(acc, r3, w3);
        }
    }
    for (; j < e; j++) {
        int2 p = __ldg(pack + j);
        float4 r = ((const float4*)(dense + (long)p.x * 256))[lane];
        macc8(acc, r, __int_as_float(p.y));
    }
}

// ---------------- F=256 dual SpMM + leaky over a row range -> fp16 ----------------
__global__ void spmm256_part(const int* __restrict__ rpA, const int2* __restrict__ packA,
                             const int* __restrict__ rpB, const int2* __restrict__ packB,
                             const __half* __restrict__ dA, const __half* __restrict__ dB,
                             __half* __restrict__ outp, int nrows) {
    int r = (blockIdx.x * blockDim.x + threadIdx.x) >> 5;
    if (r >= nrows) return;
    int lane = threadIdx.x & 31;

    float a[8] = {}, b[8] = {};
    accum256(packA, rpA[r], rpA[r + 1], dA, lane, a);
    accum256(packB, rpB[r], rpB[r + 1], dB, lane, b);

    __half2 h[4];
    #pragma unroll
    for (int q = 0; q < 4; q++)
        h[q] = __floats2half2_rn(leaky(a[q * 2]) + leaky(b[q * 2]),
                                 leaky(a[q * 2 + 1]) + leaky(b[q * 2 + 1]));
    uint4 u;
    u.x = *(unsigned*)&h[0]; u.y = *(unsigned*)&h[1];
    u.z = *(unsigned*)&h[2]; u.w = *(unsigned*)&h[3];
    *((uint4*)(outp + (long)r * 256) + lane) = u;
}

// ---------------- F=64 gather, 2 nnz per warp (half-warp per nnz) ----------------
__device__ __forceinline__ void vmacc4(float4& acc, uint2 d, float v) {
    float2 f0 = __half22float2(*(__half2*)&d.x);
    float2 f1 = __half22float2(*(__half2*)&d.y);
    acc.x += v * f0.x; acc.y += v * f0.y;
    acc.z += v * f1.x; acc.w += v * f1.y;
}

__device__ __forceinline__ void accum64v(const int2* __restrict__ pack,
                                         int s, int e, const __half* __restrict__ dense,
                                         int sub, int fl, float4& acc) {
    int j = s;
    for (; j + 4 <= e; j += 4) {
        int2 p0 = __ldg(pack + j + sub);
        int2 p1 = __ldg(pack + j + 2 + sub);
        uint2 d0 = *(const uint2*)(dense + (long)p0.x * 64 + fl * 4);
        uint2 d1 = *(const uint2*)(dense + (long)p1.x * 64 + fl * 4);
        vmacc4(acc, d0, __int_as_float(p0.y));
        vmacc4(acc, d1, __int_as_float(p1.y));
    }
    for (; j + 2 <= e; j += 2) {
        int2 p = __ldg(pack + j + sub);
        uint2 d = *(const uint2*)(dense + (long)p.x * 64 + fl * 4);
        vmacc4(acc, d, __int_as_float(p.y));
    }
    if (j < e) {
        int2 p = __ldg(pack + j);
        uint2 d = *(const uint2*)(dense + (long)p.x * 64 + fl * 4);
        float v = (sub == 0) ? __int_as_float(p.y) : 0.f;
        vmacc4(acc, d, v);
    }
}

__global__ void spmm64_all(const int* __restrict__ rp, const int2* __restrict__ pack,
                           const __half* __restrict__ dX, const __half* __restrict__ dY,
                           float* __restrict__ outbase) {
    int w = (blockIdx.x * blockDim.x + threadIdx.x) >> 5;
    if (w >= NROWS + MROWS) return;
    int lane = threadIdx.x & 31;
    int sub = lane >> 4;
    int fl  = lane & 15;

    const int* rpA; const int* rpB; long csA, csB; int r;
    if (w < NROWS) {
        r = w;
        rpA = rp + RP_HHT; csA = CS_HHT;
        rpB = rp + RP_H;   csB = CS_H;
    } else {
        r = w - NROWS;
        rpA = rp + RP_HT;  csA = CS_HT;
        rpB = rp + RP_HTH; csB = CS_HTH;
    }

    float4 a = make_float4(0, 0, 0, 0), b = a;
    accum64v(pack + csA, rpA[r], rpA[r + 1], dX, sub, fl, a);
    accum64v(pack + csB, rpB[r], rpB[r + 1], dY, sub, fl, b);

    a.x += __shfl_down_sync(0xffffffffu, a.x, 16);
    a.y += __shfl_down_sync(0xffffffffu, a.y, 16);
    a.z += __shfl_down_sync(0xffffffffu, a.z, 16);
    a.w += __shfl_down_sync(0xffffffffu, a.w, 16);
    b.x += __shfl_down_sync(0xffffffffu, b.x, 16);
    b.y += __shfl_down_sync(0xffffffffu, b.y, 16);
    b.z += __shfl_down_sync(0xffffffffu, b.z, 16);
    b.w += __shfl_down_sync(0xffffffffu, b.w, 16);

    if (sub == 0) {
        float4 res;
        res.x = leaky(a.x) + leaky(b.x);
        res.y = leaky(a.y) + leaky(b.y);
        res.z = leaky(a.z) + leaky(b.z);
        res.w = leaky(a.w) + leaky(b.w);
        ((float4*)(outbase + (long)w * 64))[fl] = res;
    }
}

// ---------------- side-stream handles ----------------
static cudaStream_t g_side = nullptr;
static cudaEvent_t  g_fork = nullptr;
static cudaEvent_t  g_evA = nullptr;
static cudaEvent_t  g_evB = nullptr;
static cudaEvent_t  g_evX = nullptr;
static cudaEvent_t  g_evG = nullptr;

extern "C" void kernel_launch(void* const* d_in, const int* in_sizes, int n_in,
                              void* d_out, int out_size) {
    const float* x  = (const float*)d_in[0];
    const float* y  = (const float*)d_in[1];
    const float* W0 = (const float*)d_in[2];
    const float* W1 = (const float*)d_in[3];
    const int*   hht_r = (const int*)d_in[4];
    const int*   hht_c = (const int*)d_in[5];
    const float* hht_v = (const float*)d_in[6];
    const int*   h_r = (const int*)d_in[7];
    const int*   h_c = (const int*)d_in[8];
    const float* h_v = (const float*)d_in[9];
    const int*   ht_r = (const int*)d_in[10];
    const int*   ht_c = (const int*)d_in[11];
    const float* ht_v = (const float*)d_in[12];
    const int*   hth_r = (const int*)d_in[13];
    const int*   hth_c = (const int*)d_in[14];
    const float* hth_v = (const float*)d_in[15];
    float* out = (float*)d_out;

    if (!g_side) {
        cudaStreamCreateWithFlags(&g_side, cudaStreamNonBlocking);
        cudaEventCreateWithFlags(&g_fork, cudaEventDisableTiming);
        cudaEventCreateWithFlags(&g_evA, cudaEventDisableTiming);
        cudaEventCreateWithFlags(&g_evB, cudaEventDisableTiming);
        cudaEventCreateWithFlags(&g_evX, cudaEventDisableTiming);
        cudaEventCreateWithFlags(&g_evG, cudaEventDisableTiming);
    }

    void* p = nullptr;
    cudaGetSymbolAddress(&p, g_hs);
    __half* H = (__half*)p;
    cudaGetSymbolAddress(&p, g_is);
    int* I = (int*)p;
    cudaGetSymbolAddress(&p, g_pack);
    int2* pack = (int2*)p;

    __half* xw0  = H + H_XW0;
    __half* yw0  = H + H_YW0;
    __half* x1h  = H + H_X1;
    __half* y1h  = H + H_Y1;
    __half* x1w1 = H + H_X1W1;
    __half* y1w1 = H + H_Y1W1;

    int* cur = I + I_CUR;
    int* rp  = I + I_RP;

    const int T = 256;
    const long SPLIT = (long)NNZ_HHT + NNZ_H;   // x-rows use HHT+H; y-rows use HT+HTH
    int nbx128 = (NROWS + 127) / 128, nby128 = (MROWS + 127) / 128;
    int nbx64  = (NROWS + 63) / 64,  nby64  = (MROWS + 63) / 64;

    // ---- fork: CSR build on side stream, layer-0 GEMM on main stream ----
    cudaEventRecord(g_fork, 0);
    cudaStreamWaitEvent(g_side, g_fork, 0);

    // side stream: CSR build part A (zero via memset node, count, scan, permute A)
    {
        int ncur = 2 * NROWS + 2 * MROWS;
        cudaMemsetAsync(cur, 0, (size_t)ncur * sizeof(int), g_side);
        count_all_k<<<(NNZ_TOT + T - 1) / T, T, 0, g_side>>>(hht_r, h_r, ht_r, hth_r, cur);
        scan_all_k<<<4, 1024, 0, g_side>>>(cur, rp);
        permute_range_k<<<(int)((SPLIT / 2 + T - 1) / T), T, 0, g_side>>>(
            hht_r, hht_c, hht_v, h_r, h_c, h_v, ht_r, ht_c, ht_v,
            hth_r, hth_c, hth_v, cur, pack, 0L, SPLIT);
        cudaEventRecord(g_evA, g_side);
    }

    // main stream: layer-0 GEMMs, 128x128 tiles (fp32 A -> fp16 mma)
    {
        dim3 g(256 / 128, nbx128 + nby128);
        gemm0_mma<<<g, T>>>(x, NROWS, y, MROWS, W0, xw0, yw0, nbx128);
    }

    // main: layer-0 SpMM x-part (needs permute A only)
    cudaStreamWaitEvent(0, g_evA, 0);
    spmm256_part<<<(NROWS + 7) / 8, T>>>(rp + RP_HHT, pack + CS_HHT,
                                         rp + RP_H,   pack + CS_H,
                                         xw0, yw0, x1h, NROWS);
    cudaEventRecord(g_evX, 0);

    // side stream: permute B (overlaps spmm256x)
    permute_range_k<<<(int)(((NNZ_TOT - SPLIT) / 2 + T - 1) / T), T, 0, g_side>>>(
        hht_r, hht_c, hht_v, h_r, h_c, h_v, ht_r, ht_c, ht_v,
        hth_r, hth_c, hth_v, cur, pack, SPLIT, (long)NNZ_TOT);
    cudaEventRecord(g_evB, g_side);

    // side stream: gemm1 x-part (needs x1h) — overlaps spmm256 y-part on main
    cudaStreamWaitEvent(g_side, g_evX, 0);
    {
        dim3 g(1, nbx64);
        gemm1_mma<<<g, T, 0, g_side>>>(x1h, NROWS, W1, x1w1);
    }
    cudaEventRecord(g_evG, g_side);

    // main: layer-0 SpMM y-part (needs permute B)
    cudaStreamWaitEvent(0, g_evB, 0);
    spmm256_part<<<(MROWS + 7) / 8, T>>>(rp + RP_HT,  pack + CS_HT,
                                         rp + RP_HTH, pack + CS_HTH,
                                         xw0, yw0, y1h, MROWS);

    // main: gemm1 y-part
    {
        dim3 g(1, nby64);
        gemm1_mma<<<g, T>>>(y1h, MROWS, W1, y1w1);
    }

    // main: layer-1 SpMM (combined) straight into d_out — needs gemm1 x-part too
    cudaStreamWaitEvent(0, g_evG, 0);
    spmm64_all<<<(NROWS + MROWS + 7) / 8, T>>>(rp, pack, x1w1, y1w1, out);
}

// round 16
// speedup vs baseline: 1.1122x; 1.0047x over previous
#include <cuda_runtime.h>
#include <cuda_fp16.h>
#include <cstdint>

// ---------------- problem constants ----------------
#define NROWS 50000
#define MROWS 20000
#define NNZ_HHT 1600000
#define NNZ_H   1000000
#define NNZ_HT  1000000
#define NNZ_HTH 640000
#define NNZ_TOT (NNZ_HHT + NNZ_H + NNZ_HT + NNZ_HTH)
#define NEG_SLOPE 0.2f

// ---------------- half scratch (element counts) ----------------
#define H_XW0   0L
#define H_YW0   (H_XW0  + 12800000L)
#define H_X1    (H_YW0  + 5120000L)
#define H_Y1    (H_X1   + 12800000L)
#define H_X1W1  (H_Y1   + 5120000L)
#define H_Y1W1  (H_X1W1 + 3200000L)
#define HS_TOT  (H_Y1W1 + 1280000L)

// ---------------- int scratch ----------------
#define I_CUR   0L
#define I_RP    (I_CUR + 2L*NROWS + 2L*MROWS)
#define IS_TOT  (I_RP  + 2L*(NROWS+1) + 2L*(MROWS+1))

#define CUR_HHT 0L
#define CUR_H   ((long)NROWS)
#define CUR_HT  (2L*NROWS)
#define CUR_HTH (2L*NROWS + MROWS)
#define RP_HHT  0L
#define RP_H    ((long)NROWS + 1)
#define RP_HT   (2L*(NROWS + 1))
#define RP_HTH  (2L*(NROWS + 1) + MROWS + 1)
#define CS_HHT  0L
#define CS_H    ((long)NNZ_HHT)
#define CS_HT   ((long)NNZ_HHT + NNZ_H)
#define CS_HTH  ((long)NNZ_HHT + NNZ_H + NNZ_HT)

__device__ __align__(16) __half g_hs[HS_TOT];
__device__ __align__(16) int    g_is[IS_TOT];
__device__ __align__(16) int2   g_pack[NNZ_TOT];

__device__ __forceinline__ float leaky(float v) {
    return v >= 0.f ? v : NEG_SLOPE * v;
}

// ---------------- CSR build: count ----------------
__global__ void count_all_k(const int* __restrict__ r0, const int* __restrict__ r1,
                            const int* __restrict__ r2, const int* __restrict__ r3,
                            int* __restrict__ cur) {
    long i = (long)blockIdx.x * blockDim.x + threadIdx.x;
    if (i >= NNZ_TOT) return;
    if (i < NNZ_HHT) {
        atomicAdd(&cur[CUR_HHT + r0[i]], 1);
    } else if (i < NNZ_HHT + NNZ_H) {
        atomicAdd(&cur[CUR_H + r1[i - NNZ_HHT]], 1);
    } else if (i < NNZ_HHT + NNZ_H + NNZ_HT) {
        atomicAdd(&cur[CUR_HT + r2[i - NNZ_HHT - NNZ_H]], 1);
    } else {
        atomicAdd(&cur[CUR_HTH + r3[i - NNZ_HHT - NNZ_H - NNZ_HT]], 1);
    }
}

// ---------------- CSR build: fast single-pass scan (4 blocks) ----------------
__global__ void scan_all_k(int* __restrict__ cur, int* __restrict__ rp) {
    __shared__ int wsum[32];
    int b = blockIdx.x;
    int n; int* cnt; int* rowp;
    if (b == 0)      { n = NROWS; cnt = cur + CUR_HHT; rowp = rp + RP_HHT; }
    else if (b == 1) { n = NROWS; cnt = cur + CUR_H;   rowp = rp + RP_H;   }
    else if (b == 2) { n = MROWS; cnt = cur + CUR_HT;  rowp = rp + RP_HT;  }
    else             { n = MROWS; cnt = cur + CUR_HTH; rowp = rp + RP_HTH; }

    int t = threadIdx.x;            // 1024 threads
    int lane = t & 31, wid = t >> 5;
    int CH = (n + 1023) >> 10;
    int s0 = t * CH; if (s0 > n) s0 = n;
    int s1 = s0 + CH; if (s1 > n) s1 = n;

    int sum = 0;
    for (int i = s0; i < s1; i++) sum += cnt[i];

    int v = sum;
    #pragma unroll
    for (int o = 1; o < 32; o <<= 1) {
        int u = __shfl_up_sync(0xffffffffu, v, o);
        if (lane >= o) v += u;
    }
    if (lane == 31) wsum[wid] = v;
    __syncthreads();
    if (wid == 0) {
        int w = wsum[lane];
        #pragma unroll
        for (int o = 1; o < 32; o <<= 1) {
            int u = __shfl_up_sync(0xffffffffu, w, o);
            if (lane >= o) w += u;
        }
        wsum[lane] = w;
    }
    __syncthreads();
    int excl = v - sum + (wid ? wsum[wid - 1] : 0);

    int run = excl;
    for (int i = s0; i < s1; i++) {
        int c = cnt[i];
        rowp[i] = run;
        cnt[i] = run;
        run += c;
    }
    if (t == 1023) rowp[n] = run;
}

// ---------------- CSR build: permute over a range, ILP=2 ----------------
struct Ent { int r, c; float v; long cs; int* cu; };

__device__ __forceinline__ Ent load_ent(long i,
    const int* r0, const int* c0, const float* v0,
    const int* r1, const int* c1, const float* v1,
    const int* r2, const int* c2, const float* v2,
    const int* r3, const int* c3, const float* v3, int* cur) {
    Ent e;
    if (i < NNZ_HHT) {
        e.r = r0[i]; e.c = c0[i]; e.v = v0[i]; e.cs = CS_HHT; e.cu = cur + CUR_HHT;
    } else if (i < NNZ_HHT + NNZ_H) {
        long j = i - NNZ_HHT;
        e.r = r1[j]; e.c = c1[j]; e.v = v1[j]; e.cs = CS_H; e.cu = cur + CUR_H;
    } else if (i < NNZ_HHT + NNZ_H + NNZ_HT) {
        long j = i - NNZ_HHT - NNZ_H;
        e.r = r2[j]; e.c = c2[j]; e.v = v2[j]; e.cs = CS_HT; e.cu = cur + CUR_HT;
    } else {
        long j = i - NNZ_HHT - NNZ_H - NNZ_HT;
        e.r = r3[j]; e.c = c3[j]; e.v = v3[j]; e.cs = CS_HTH; e.cu = cur + CUR_HTH;
    }
    return e;
}

__global__ void permute_range_k(const int* __restrict__ r0, const int* __restrict__ c0, const float* __restrict__ v0,
                                const int* __restrict__ r1, const int* __restrict__ c1, const float* __restrict__ v1,
                                const int* __restrict__ r2, const int* __restrict__ c2, const float* __restrict__ v2,
                                const int* __restrict__ r3, const int* __restrict__ c3, const float* __restrict__ v3,
                                int* __restrict__ cur, int2* __restrict__ pack,
                                long start, long end) {
    long i = start + ((long)blockIdx.x * blockDim.x + threadIdx.x) * 2;
    if (i >= end) return;
    Ent e0 = load_ent(i, r0,c0,v0, r1,c1,v1, r2,c2,v2, r3,c3,v3, cur);
    bool two = (i + 1 < end);
    Ent e1;
    if (two) e1 = load_ent(i + 1, r0,c0,v0, r1,c1,v1, r2,c2,v2, r3,c3,v3, cur);
    int s0 = atomicAdd(&e0.cu[e0.r], 1);
    pack[e0.cs + s0] = make_int2(e0.c, __float_as_int(e0.v));
    if (two) {
        int s1 = atomicAdd(&e1.cu[e1.r], 1);
        pack[e1.cs + s1] = make_int2(e1.c, __float_as_int(e1.v));
    }
}

// ---------------- mma primitive ----------------
__device__ __forceinline__ void mma16816(float* c, const unsigned* a, const unsigned* b) {
    asm volatile("mma.sync.aligned.m16n8k16.row.col.f32.f16.f16.f32 "
                 "{%0,%1,%2,%3}, {%4,%5,%6,%7}, {%8,%9}, {%0,%1,%2,%3};"
                 : "+f"(c[0]), "+f"(c[1]), "+f"(c[2]), "+f"(c[3])
                 : "r"(a[0]), "r"(a[1]), "r"(a[2]), "r"(a[3]),
                   "r"(b[0]), "r"(b[1]));
}

// ---------------- layer-0 GEMM: 128x128 tiles, double-buffered pipeline ----------------
__global__ __launch_bounds__(256, 2)
void gemm0_mma(const float* __restrict__ A1, int Rows1,
               const float* __restrict__ A2, int Rows2,
               const float* __restrict__ W,
               __half* __restrict__ C1, __half* __restrict__ C2,
               int nb1) {
    const int BK = 32;
    __shared__ __align__(16) __half As[2][128][40];   // 2 x 10 KB
    __shared__ __align__(16) __half Bs[2][128][40];   // 2 x 10 KB

    const float* A;
    __half* C;
    int Rows, m0;
    if ((int)blockIdx.y < nb1) { A = A1; C = C1; Rows = Rows1; m0 = blockIdx.y * 128; }
    else                        { A = A2; C = C2; Rows = Rows2; m0 = (blockIdx.y - nb1) * 128; }

    int tid = threadIdx.x;        // 256
    int lane = tid & 31, warp = tid >> 5;
    int wm = warp >> 2;           // 0..1 -> 64 rows each
    int wn = warp & 3;            // 0..3 -> 32 cols each
    int n0 = blockIdx.x * 128;

    // per-thread load coordinates
    int am  = tid >> 1;
    int akc = (tid & 1) * 16;
    bool arow_ok = (m0 + am < Rows);
    const float* asrc0 = A + (long)(m0 + am) * 256 + akc;
    int bn  = tid & 127;
    int bkb = (tid >> 7) * 16;
    const float* wsrc0 = W + (long)bkb * 256 + n0 + bn;

    float c[4][4][4] = {};
    float4 pa[4];
    float  pw[16];

    // prefetch tile k0 = 0
    if (arow_ok) {
        #pragma unroll
        for (int q = 0; q < 4; q++) pa[q] = *(const float4*)(asrc0 + q * 4);
    } else {
        #pragma unroll
        for (int q = 0; q < 4; q++) pa[q] = make_float4(0, 0, 0, 0);
    }
    #pragma unroll
    for (int q = 0; q < 16; q++) pw[q] = wsrc0[(long)q * 256];

    int buf = 0;
    // store tile 0
    {
        __half h[16];
        #pragma unroll
        for (int q = 0; q < 4; q++) {
            h[q * 4 + 0] = __float2half(pa[q].x); h[q * 4 + 1] = __float2half(pa[q].y);
            h[q * 4 + 2] = __float2half(pa[q].z); h[q * 4 + 3] = __float2half(pa[q].w);
        }
        *(uint4*)&As[buf][am][akc]     = *(uint4*)&h[0];
        *(uint4*)&As[buf][am][akc + 8] = *(uint4*)&h[8];
        __half hw[16];
        #pragma unroll
        for (int q = 0; q < 16; q++) hw[q] = __float2half(pw[q]);
        *(uint4*)&Bs[buf][bn][bkb]     = *(uint4*)&hw[0];
        *(uint4*)&Bs[buf][bn][bkb + 8] = *(uint4*)&hw[8];
    }
    __syncthreads();

    for (int k0 = 0; k0 < 256; k0 += BK) {
        bool has_next = (k0 + BK < 256);
        // (a) prefetch next tile into registers
        if (has_next) {
            if (arow_ok) {
                const float* src = asrc0 + k0 + BK;
                #pragma unroll
                for (int q = 0; q < 4; q++) pa[q] = *(const float4*)(src + q * 4);
            }
            const float* wsrc = wsrc0 + (long)(k0 + BK) * 256;
            #pragma unroll
            for (int q = 0; q < 16; q++) pw[q] = wsrc[(long)q * 256];
        }

        // (b) compute current tile from smem[buf]
        #pragma unroll
        for (int ks = 0; ks < 2; ks++) {
            int kk = ks * 16;
            int gr = lane >> 2;
            int gk = (lane & 3) * 2;
            unsigned bf[4][2];
            #pragma unroll
            for (int j = 0; j < 4; j++) {
                int nn = wn * 32 + j * 8 + gr;
                bf[j][0] = *(const unsigned*)&Bs[buf][nn][kk + gk];
                bf[j][1] = *(const unsigned*)&Bs[buf][nn][kk + gk + 8];
            }
            #pragma unroll
            for (int i = 0; i < 4; i++) {
                int r = wm * 64 + i * 16 + gr;
                unsigned a[4];
                a[0] = *(const unsigned*)&As[buf][r][kk + gk];
                a[1] = *(const unsigned*)&As[buf][r + 8][kk + gk];
                a[2] = *(const unsigned*)&As[buf][r][kk + gk + 8];
                a[3] = *(const unsigned*)&As[buf][r + 8][kk + gk + 8];
                #pragma unroll
                for (int j = 0; j < 4; j++)
                    mma16816(c[i][j], a, bf[j]);
            }
        }

        // (c) store prefetched tile into the other buffer
        if (has_next) {
            int nb = buf ^ 1;
            __half h[16];
            #pragma unroll
            for (int q = 0; q < 4; q++) {
                h[q * 4 + 0] = __float2half(pa[q].x); h[q * 4 + 1] = __float2half(pa[q].y);
                h[q * 4 + 2] = __float2half(pa[q].z); h[q * 4 + 3] = __float2half(pa[q].w);
            }
            if (!arow_ok) {
                #pragma unroll
                for (int q = 0; q < 16; q++) h[q] = __float2half(0.f);
            }
            *(uint4*)&As[nb][am][akc]     = *(uint4*)&h[0];
            *(uint4*)&As[nb][am][akc + 8] = *(uint4*)&h[8];
            __half hw[16];
            #pragma unroll
            for (int q = 0; q < 16; q++) hw[q] = __float2half(pw[q]);
            *(uint4*)&Bs[nb][bn][bkb]     = *(uint4*)&hw[0];
            *(uint4*)&Bs[nb][bn][bkb + 8] = *(uint4*)&hw[8];
            __syncthreads();
            buf = nb;
        }
    }

    // --- epilogue: fp32 acc -> fp16 store ---
    int gr = lane >> 2;
    int gc = (lane & 3) * 2;
    #pragma unroll
    for (int i = 0; i < 4; i++) {
        #pragma unroll
        for (int j = 0; j < 4; j++) {
            int rg = m0 + wm * 64 + i * 16 + gr;
            int cg = n0 + wn * 32 + j * 8 + gc;
            if (rg < Rows) {
                __half2 h = __floats2half2_rn(c[i][j][0], c[i][j][1]);
                *(__half2*)(C + (long)rg * 256 + cg) = h;
            }
            if (rg + 8 < Rows) {
                __half2 h = __floats2half2_rn(c[i][j][2], c[i][j][3]);
                *(__half2*)(C + (long)(rg + 8) * 256 + cg) = h;
            }
        }
    }
}

// ---------------- layer-1 GEMM: 64x64 tiles, fp16 A, Ncols=64 ----------------
__global__ void gemm1_mma(const __half* __restrict__ A, int Rows,
                          const float* __restrict__ W,
                          __half* __restrict__ C) {
    const int BK = 32;
    __shared__ __align__(16) __half As[64][40];
    __shared__ __align__(16) __half Bs[64][40];

    int m0 = blockIdx.y * 64;
    int tid = threadIdx.x;
    int lane = tid & 31, warp = tid >> 5;
    int wm = warp >> 2;
    int wn = warp & 3;

    float c[2][2][4] = {};

    for (int k0 = 0; k0 < 256; k0 += BK) {
        {
            int m  = tid >> 2;
            int kc = (tid & 3) * 8;
            int gm = m0 + m;
            __half h[8];
            if (gm < Rows) {
                *(uint4*)h = *(const uint4*)(A + (long)gm * 256 + k0 + kc);
            } else {
                #pragma unroll
                for (int q = 0; q < 8; q++) h[q] = __float2half(0.f);
            }
            *(uint4*)&As[m][kc] = *(uint4*)h;
        }
        {
            int n  = tid & 63;
            int k8 = (tid >> 6) * 8;
            #pragma unroll
            for (int q = 0; q < 8; q++) {
                float w = W[(long)(k0 + k8 + q) * 64 + n];
                Bs[n][k8 + q] = __float2half(w);
            }
        }
        __syncthreads();

        #pragma unroll
        for (int ks = 0; ks < 2; ks++) {
            int kk = ks * 16;
            int gr = lane >> 2;
            int gk = (lane & 3) * 2;
            unsigned bf[2][2];
            #pragma unroll
            for (int j = 0; j < 2; j++) {
                int nn = wn * 16 + j * 8 + gr;
                bf[j][0] = *(const unsigned*)&Bs[nn][kk + gk];
                bf[j][1] = *(const unsigned*)&Bs[nn][kk + gk + 8];
            }
            #pragma unroll
            for (int i = 0; i < 2; i++) {
                int r = wm * 32 + i * 16 + gr;
                unsigned a[4];
                a[0] = *(const unsigned*)&As[r][kk + gk];
                a[1] = *(const unsigned*)&As[r + 8][kk + gk];
                a[2] = *(const unsigned*)&As[r][kk + gk + 8];
                a[3] = *(const unsigned*)&As[r + 8][kk + gk + 8];
                mma16816(c[i][0], a, bf[0]);
                mma16816(c[i][1], a, bf[1]);
            }
        }
        __syncthreads();
    }

    int gr = lane >> 2;
    int gc = (lane & 3) * 2;
    #pragma unroll
    for (int i = 0; i < 2; i++) {
        #pragma unroll
        for (int j = 0; j < 2; j++) {
            int rg = m0 + wm * 32 + i * 16 + gr;
            int cg = wn * 16 + j * 8 + gc;
            if (rg < Rows) {
                __half2 h = __floats2half2_rn(c[i][j][0], c[i][j][1]);
                *(__half2*)(C + (long)rg * 64 + cg) = h;
            }
            if (rg + 8 < Rows) {
                __half2 h = __floats2half2_rn(c[i][j][2], c[i][j][3]);
                *(__half2*)(C + (long)(rg + 8) * 64 + cg) = h;
            }
        }
    }
}

// ---------------- F=256 gather accumulate, MLP=4 ----------------
__device__ __forceinline__ void macc8(float* acc, float4 raw, float v) {
    const __half2* h = (const __half2*)&raw;
    #pragma unroll
    for (int q = 0; q < 4; q++) {
        float2 f = __half22float2(h[q]);
        acc[q * 2 + 0] += v * f.x;
        acc[q * 2 + 1] += v * f.y;
    }
}

__device__ __forceinline__ void accum256(const int2* __restrict__ pack,
                                         int s, int e, const __half* __restrict__ dense,
                                         int lane, float* acc) {
    int j = s;
    if (j + 4 <= e) {
        int2 p0 = __ldg(pack + j),     p1 = __ldg(pack + j + 1);
        int2 p2 = __ldg(pack + j + 2), p3 = __ldg(pack + j + 3);
        for (; j + 4 <= e; ) {
            float4 r0 = ((const float4*)(dense + (long)p0.x * 256))[lane];
            float4 r1 = ((const float4*)(dense + (long)p1.x * 256))[lane];
            float4 r2 = ((const float4*)(dense + (long)p2.x * 256))[lane];
            float4 r3 = ((const float4*)(dense + (long)p3.x * 256))[lane];
            float w0 = __int_as_float(p0.y), w1 = __int_as_float(p1.y);
            float w2 = __int_as_float(p2.y), w3 = __int_as_float(p3.y);
            j += 4;
            if (j + 4 <= e) {
                p0 = __ldg(pack + j);     p1 = __ldg(pack + j + 1);
                p2 = __ldg(pack + j + 2); p3 = __ldg(pack + j + 3);
            }
            macc8(acc, r0, w0);
            macc8(acc, r1, w1);
            macc8(acc, r2, w2);
            macc8(acc, r3, w3);
        }
    }
    for (; j < e; j++) {
        int2 p = __ldg(pack + j);
        float4 r = ((const float4*)(dense + (long)p.x * 256))[lane];
        macc8(acc, r, __int_as_float(p.y));
    }
}

// ---------------- F=256 dual SpMM + leaky over a row range -> fp16 ----------------
__global__ void spmm256_part(const int* __restrict__ rpA, const int2* __restrict__ packA,
                             const int* __restrict__ rpB, const int2* __restrict__ packB,
                             const __half* __restrict__ dA, const __half* __restrict__ dB,
                             __half* __restrict__ outp, int nrows) {
    int r = (blockIdx.x * blockDim.x + threadIdx.x) >> 5;
    if (r >= nrows) return;
    int lane = threadIdx.x & 31;

    float a[8] = {}, b[8] = {};
    accum256(packA, rpA[r], rpA[r + 1], dA, lane, a);
    accum256(packB, rpB[r], rpB[r + 1], dB, lane, b);

    __half2 h[4];
    #pragma unroll
    for (int q = 0; q < 4; q++)
        h[q] = __floats2half2_rn(leaky(a[q * 2]) + leaky(b[q * 2]),
                                 leaky(a[q * 2 + 1]) + leaky(b[q * 2 + 1]));
    uint4 u;
    u.x = *(unsigned*)&h[0]; u.y = *(unsigned*)&h[1];
    u.z = *(unsigned*)&h[2]; u.w = *(unsigned*)&h[3];
    *((uint4*)(outp + (long)r * 256) + lane) = u;
}

// ---------------- F=64 gather, 2 nnz per warp (half-warp per nnz) ----------------
__device__ __forceinline__ void vmacc4(float4& acc, uint2 d, float v) {
    float2 f0 = __half22float2(*(__half2*)&d.x);
    float2 f1 = __half22float2(*(__half2*)&d.y);
    acc.x += v * f0.x; acc.y += v * f0.y;
    acc.z += v * f1.x; acc.w += v * f1.y;
}

__device__ __forceinline__ void accum64v(const int2* __restrict__ pack,
                                         int s, int e, const __half* __restrict__ dense,
                                         int sub, int fl, float4& acc) {
    int j = s;
    for (; j + 4 <= e; j += 4) {
        int2 p0 = __ldg(pack + j + sub);
        int2 p1 = __ldg(pack + j + 2 + sub);
        uint2 d0 = *(const uint2*)(dense + (long)p0.x * 64 + fl * 4);
        uint2 d1 = *(const uint2*)(dense + (long)p1.x * 64 + fl * 4);
        vmacc4(acc, d0, __int_as_float(p0.y));
        vmacc4(acc, d1, __int_as_float(p1.y));
    }
    for (; j + 2 <= e; j += 2) {
        int2 p = __ldg(pack + j + sub);
        uint2 d = *(const uint2*)(dense + (long)p.x * 64 + fl * 4);
        vmacc4(acc, d, __int_as_float(p.y));
    }
    if (j < e) {
        int2 p = __ldg(pack + j);
        uint2 d = *(const uint2*)(dense + (long)p.x * 64 + fl * 4);
        float v = (sub == 0) ? __int_as_float(p.y) : 0.f;
        vmacc4(acc, d, v);
    }
}

__global__ void spmm64_all(const int* __restrict__ rp, const int2* __restrict__ pack,
                           const __half* __restrict__ dX, const __half* __restrict__ dY,
                           float* __restrict__ outbase) {
    int w = (blockIdx.x * blockDim.x + threadIdx.x) >> 5;
    if (w >= NROWS + MROWS) return;
    int lane = threadIdx.x & 31;
    int sub = lane >> 4;
    int fl  = lane & 15;

    const int* rpA; const int* rpB; long csA, csB; int r;
    if (w < NROWS) {
        r = w;
        rpA = rp + RP_HHT; csA = CS_HHT;
        rpB = rp + RP_H;   csB = CS_H;
    } else {
        r = w - NROWS;
        rpA = rp + RP_HT;  csA = CS_HT;
        rpB = rp + RP_HTH; csB = CS_HTH;
    }

    float4 a = make_float4(0, 0, 0, 0), b = a;
    accum64v(pack + csA, rpA[r], rpA[r + 1], dX, sub, fl, a);
    accum64v(pack + csB, rpB[r], rpB[r + 1], dY, sub, fl, b);

    a.x += __shfl_down_sync(0xffffffffu, a.x, 16);
    a.y += __shfl_down_sync(0xffffffffu, a.y, 16);
    a.z += __shfl_down_sync(0xffffffffu, a.z, 16);
    a.w += __shfl_down_sync(0xffffffffu, a.w, 16);
    b.x += __shfl_down_sync(0xffffffffu, b.x, 16);
    b.y += __shfl_down_sync(0xffffffffu, b.y, 16);
    b.z += __shfl_down_sync(0xffffffffu, b.z, 16);
    b.w += __shfl_down_sync(0xffffffffu, b.w, 16);

    if (sub == 0) {
        float4 res;
        res.x = leaky(a.x) + leaky(b.x);
        res.y = leaky(a.y) + leaky(b.y);
        res.z = leaky(a.z) + leaky(b.z);
        res.w = leaky(a.w) + leaky(b.w);
        ((float4*)(outbase + (long)w * 64))[fl] = res;
    }
}

// ---------------- side-stream handles ----------------
static cudaStream_t g_side = nullptr;
static cudaEvent_t  g_fork = nullptr;
static cudaEvent_t  g_evA = nullptr;
static cudaEvent_t  g_evB = nullptr;
static cudaEvent_t  g_evX = nullptr;
static cudaEvent_t  g_evG = nullptr;

extern "C" void kernel_launch(void* const* d_in, const int* in_sizes, int n_in,
                              void* d_out, int out_size) {
    const float* x  = (const float*)d_in[0];
    const float* y  = (const float*)d_in[1];
    const float* W0 = (const float*)d_in[2];
    const float* W1 = (const float*)d_in[3];
    const int*   hht_r = (const int*)d_in[4];
    const int*   hht_c = (const int*)d_in[5];
    const float* hht_v = (const float*)d_in[6];
    const int*   h_r = (const int*)d_in[7];
    const int*   h_c = (const int*)d_in[8];
    const float* h_v = (const float*)d_in[9];
    const int*   ht_r = (const int*)d_in[10];
    const int*   ht_c = (const int*)d_in[11];
    const float* ht_v = (const float*)d_in[12];
    const int*   hth_r = (const int*)d_in[13];
    const int*   hth_c = (const int*)d_in[14];
    const float* hth_v = (const float*)d_in[15];
    float* out = (float*)d_out;

    if (!g_side) {
        cudaStreamCreateWithFlags(&g_side, cudaStreamNonBlocking);
        cudaEventCreateWithFlags(&g_fork, cudaEventDisableTiming);
        cudaEventCreateWithFlags(&g_evA, cudaEventDisableTiming);
        cudaEventCreateWithFlags(&g_evB, cudaEventDisableTiming);
        cudaEventCreateWithFlags(&g_evX, cudaEventDisableTiming);
        cudaEventCreateWithFlags(&g_evG, cudaEventDisableTiming);
    }

    void* p = nullptr;
    cudaGetSymbolAddress(&p, g_hs);
    __half* H = (__half*)p;
    cudaGetSymbolAddress(&p, g_is);
    int* I = (int*)p;
    cudaGetSymbolAddress(&p, g_pack);
    int2* pack = (int2*)p;

    __half* xw0  = H + H_XW0;
    __half* yw0  = H + H_YW0;
    __half* x1h  = H + H_X1;
    __half* y1h  = H + H_Y1;
    __half* x1w1 = H + H_X1W1;
    __half* y1w1 = H + H_Y1W1;

    int* cur = I + I_CUR;
    int* rp  = I + I_RP;

    const int T = 256;
    const long SPLIT = (long)NNZ_HHT + NNZ_H;   // x-rows use HHT+H; y-rows use HT+HTH
    int nbx128 = (NROWS + 127) / 128, nby128 = (MROWS + 127) / 128;
    int nbx64  = (NROWS + 63) / 64,  nby64  = (MROWS + 63) / 64;

    // ---- fork: CSR build on side stream, layer-0 GEMM on main stream ----
    cudaEventRecord(g_fork, 0);
    cudaStreamWaitEvent(g_side, g_fork, 0);

    // side stream: CSR build part A (zero via memset node, count, scan, permute A)
    {
        int ncur = 2 * NROWS + 2 * MROWS;
        cudaMemsetAsync(cur, 0, (size_t)ncur * sizeof(int), g_side);
        count_all_k<<<(NNZ_TOT + T - 1) / T, T, 0, g_side>>>(hht_r, h_r, ht_r, hth_r, cur);
        scan_all_k<<<4, 1024, 0, g_side>>>(cur, rp);
        permute_range_k<<<(int)((SPLIT / 2 + T - 1) / T), T, 0, g_side>>>(
            hht_r, hht_c, hht_v, h_r, h_c, h_v, ht_r, ht_c, ht_v,
            hth_r, hth_c, hth_v, cur, pack, 0L, SPLIT);
        cudaEventRecord(g_evA, g_side);
    }

    // main stream: layer-0 GEMMs, 128x128 tiles, double-buffered
    {
        dim3 g(256 / 128, nbx128 + nby128);
        gemm0_mma<<<g, T>>>(x, NROWS, y, MROWS, W0, xw0, yw0, nbx128);
    }

    // main: layer-0 SpMM x-part (needs permute A only)
    cudaStreamWaitEvent(0, g_evA, 0);
    spmm256_part<<<(NROWS + 7) / 8, T>>>(rp + RP_HHT, pack + CS_HHT,
                                         rp + RP_H,   pack + CS_H,
                                         xw0, yw0, x1h, NROWS);
    cudaEventRecord(g_evX, 0);

    // side stream: permute B (overlaps spmm256x)
    permute_range_k<<<(int)(((NNZ_TOT - SPLIT) / 2 + T - 1) / T), T, 0, g_side>>>(
        hht_r, hht_c, hht_v, h_r, h_c, h_v, ht_r, ht_c, ht_v,
        hth_r, hth_c, hth_v, cur, pack, SPLIT, (long)NNZ_TOT);
    cudaEventRecord(g_evB, g_side);

    // side stream: gemm1 x-part (needs x1h) — overlaps spmm256 y-part on main
    cudaStreamWaitEvent(g_side, g_evX, 0);
    {
        dim3 g(1, nbx64);
        gemm1_mma<<<g, T, 0, g_side>>>(x1h, NROWS, W1, x1w1);
    }
    cudaEventRecord(g_evG, g_side);

    // main: layer-0 SpMM y-part (needs permute B)
    cudaStreamWaitEvent(0, g_evB, 0);
    spmm256_part<<<(MROWS + 7) / 8, T>>>(rp + RP_HT,  pack + CS_HT,
                                         rp + RP_HTH, pack + CS_HTH,
                                         xw0, yw0, y1h, MROWS);

    // main: gemm1 y-part
    {
        dim3 g(1, nby64);
        gemm1_mma<<<g, T>>>(y1h, MROWS, W1, y1w1);
    }

    // main: layer-1 SpMM (combined) straight into d_out — needs gemm1 x-part too
    cudaStreamWaitEvent(0, g_evG, 0);
    spmm64_all<<<(NROWS + MROWS + 7) / 8, T>>>(rp, pack, x1w1, y1w1, out);
}